// round 5
// baseline (speedup 1.0000x reference)
#include <cuda_runtime.h>
#include <math.h>

#define B_    64
#define T_    512
#define F_    64
#define H_    512
#define G_    2048          // 4*H
#define M_    (B_*T_)       // 32768
#define NCTA_ 128
#define HS_   520           // padded h_s row stride (bank-conflict-free)

typedef unsigned long long ull;

// ---------------- packed f32x2 helpers (validated round 4) ----------------
__device__ __forceinline__ void ffma2(ull& acc, ull a, ull b) {
    asm("fma.rn.f32x2 %0, %1, %2, %0;" : "+l"(acc) : "l"(a), "l"(b));
}
__device__ __forceinline__ void fadd2(ull& acc, ull b) {
    asm("add.rn.f32x2 %0, %0, %1;" : "+l"(acc) : "l"(b));
}
__device__ __forceinline__ ull pack2(float lo, float hi) {
    ull r; asm("mov.b64 %0, {%1, %2};" : "=l"(r) : "f"(lo), "f"(hi)); return r;
}
__device__ __forceinline__ void unpack2(ull v, float& lo, float& hi) {
    asm("mov.b64 {%0, %1}, %2;" : "=f"(lo), "=f"(hi) : "l"(v));
}

// ---------------- scratch (static device allocations only) ----------------
__device__ float g_xT[(size_t)F_ * M_];        //   8 MB : x transposed [F][M]
__device__ float g_xw[(size_t)M_ * G_];        // 256 MB : xW' (+bias), permuted cols
__device__ float g_hseqT[(size_t)H_ * M_];     //  64 MB : layer-1 h transposed [H][M]
__device__ float g_hbuf[2 * B_ * H_];          // double-buffered h state [buf][b][k]
__device__ float g_Wi1p[(size_t)F_ * G_];      // gate-permuted weights
__device__ float g_Wi2p[(size_t)H_ * G_];
__device__ float g_Wh1p[(size_t)H_ * G_];
__device__ float g_Wh2p[(size_t)H_ * G_];
__device__ float g_b1p[G_];
__device__ float g_b2p[G_];
__device__ unsigned g_cnt4[4 * 32];            // one counter per 128-B line
__device__ unsigned g_gen4[4 * 32];

// ---- per-batch-group barrier: round-1 proven algorithm, 32 CTAs, disjoint counters ----
__device__ __forceinline__ void group_barrier(int bg)
{
    __syncthreads();
    if (threadIdx.x == 0) {
        unsigned* cntp = &g_cnt4[bg * 32];
        unsigned* genp = &g_gen4[bg * 32];
        __threadfence();
        unsigned gen = atomicAdd(genp, 0u);
        __threadfence();
        unsigned arrived = atomicAdd(cntp, 1u);
        if (arrived == 31u) {
            atomicExch(cntp, 0u);
            __threadfence();
            atomicAdd(genp, 1u);
        } else {
            while (atomicAdd(genp, 0u) == gen) { __nanosleep(64); }
        }
        __threadfence();
    }
    __syncthreads();
}

// ---------------- column permutation: new col c' = 4*hidden + gate ----------------
__global__ void __launch_bounds__(256) reorder_cols(const float* __restrict__ src,
                                                    float* __restrict__ dst, int K)
{
    int i = blockIdx.x * 256 + threadIdx.x;
    if (i < K * G_) {
        int c = i & (G_ - 1);
        int k = i >> 11;
        dst[i] = src[(size_t)k * G_ + ((c & 3) << 9) + (c >> 2)];
    }
}
__global__ void __launch_bounds__(256) reorder_bias(const float* __restrict__ b,
                                                    float* __restrict__ bp)
{
    int c = blockIdx.x * 256 + threadIdx.x;
    if (c < G_) bp[c] = b[((c & 3) << 9) + (c >> 2)];
}

// ---------------- x transpose: x[M][F] -> xT[F][M] (round-1 verbatim) ----------------
__global__ void __launch_bounds__(256) transpose_x(const float* __restrict__ x,
                                                   float* __restrict__ xT)
{
    __shared__ float tile[32][33];
    const int m0 = blockIdx.x * 32;
    const int f0 = blockIdx.y * 32;
    const int tx = threadIdx.x, ty = threadIdx.y;
#pragma unroll
    for (int i = 0; i < 32; i += 8)
        tile[ty + i][tx] = x[(size_t)(m0 + ty + i) * F_ + f0 + tx];
    __syncthreads();
#pragma unroll
    for (int i = 0; i < 32; i += 8)
        xT[(size_t)(f0 + ty + i) * M_ + m0 + tx] = tile[tx][ty + i];
}

// ---------------- GEMM (round-4 verbatim, proven) ----------------
__global__ void __launch_bounds__(256) gemm_atb(const float* __restrict__ AT,
                                                const float* __restrict__ Bm,
                                                const float* __restrict__ bias,
                                                float* __restrict__ C,
                                                int M, int N, int K)
{
    __shared__ float As[2][16 * 64];
    __shared__ float Bs[2][16 * 64];
    const int tid = threadIdx.x;
    const int tx = tid & 15, ty = tid >> 4;
    const int m0 = blockIdx.y * 64, n0 = blockIdx.x * 64;
    const int lr = tid >> 4, lc4 = (tid & 15) * 4;

    const float* ap = AT + (size_t)lr * M + m0 + lc4;
    const float* bp = Bm + (size_t)lr * N + n0 + lc4;
    float4 aReg = *(const float4*)ap;
    float4 bReg = *(const float4*)bp;

    ull accP[4][2];
#pragma unroll
    for (int i = 0; i < 4; i++) { accP[i][0] = 0ull; accP[i][1] = 0ull; }

    const int NT = K >> 4;
    for (int kt = 0; kt < NT; kt++) {
        const int cur = kt & 1;
        *(float4*)&As[cur][lr * 64 + lc4] = aReg;
        *(float4*)&Bs[cur][lr * 64 + lc4] = bReg;
        __syncthreads();
        if (kt + 1 < NT) {
            aReg = *(const float4*)(ap + (size_t)(kt + 1) * 16 * M);
            bReg = *(const float4*)(bp + (size_t)(kt + 1) * 16 * N);
        }
#pragma unroll
        for (int kk = 0; kk < 16; kk++) {
            float4 a = *(const float4*)&As[cur][kk * 64 + ty * 4];
            ulonglong2 bv = *(const ulonglong2*)&Bs[cur][kk * 64 + tx * 4];
            ull a0 = pack2(a.x, a.x);
            ull a1 = pack2(a.y, a.y);
            ull a2 = pack2(a.z, a.z);
            ull a3 = pack2(a.w, a.w);
            ffma2(accP[0][0], a0, bv.x); ffma2(accP[0][1], a0, bv.y);
            ffma2(accP[1][0], a1, bv.x); ffma2(accP[1][1], a1, bv.y);
            ffma2(accP[2][0], a2, bv.x); ffma2(accP[2][1], a2, bv.y);
            ffma2(accP[3][0], a3, bv.x); ffma2(accP[3][1], a3, bv.y);
        }
    }
    float acc[4][4];
#pragma unroll
    for (int i = 0; i < 4; i++) {
        unpack2(accP[i][0], acc[i][0], acc[i][1]);
        unpack2(accP[i][1], acc[i][2], acc[i][3]);
    }
    float4 bv = *(const float4*)(bias + n0 + tx * 4);
#pragma unroll
    for (int i = 0; i < 4; i++) {
        float4 o;
        o.x = acc[i][0] + bv.x;
        o.y = acc[i][1] + bv.y;
        o.z = acc[i][2] + bv.z;
        o.w = acc[i][3] + bv.w;
        *(float4*)&C[(size_t)(m0 + ty * 4 + i) * N + n0 + tx * 4] = o;
    }
}

// ---------------- persistent LSTM layer (batch-group partitioning) ----------------
// 128 CTAs = 4 batch-groups (16 b) x 32 col-groups (64 gate cols = 16 hidden).
// SMEM: Wh' slice [512][64] loaded once (128KB); h_s [16][HS_] staged per step (32KB).
// Cell state in registers. Permuted cols: c' = 4*hidden + gate(i,f,g,o).
__global__ void __launch_bounds__(256, 1) lstm_persistent(const float* __restrict__ xw,
                                                          const float* __restrict__ Whp,
                                                          float* __restrict__ hseqT)
{
    extern __shared__ float sm[];
    float* w_s = sm;                          // 512*64 = 32768 floats
    float* h_s = sm + 32768;                  // 16*520 =  8320 floats
    ull*   red = (ull*)(sm + 32768 + 8320);   // 128*4 ull = 4096 B

    const int tid = threadIdx.x;
    const int cg  = blockIdx.x & 31;
    const int bg  = blockIdx.x >> 5;

    const int q      = tid >> 7;              // k-half [q*256, q*256+256)
    const int r      = tid & 127;
    const int b_loc  = r >> 3;                // 0..15
    const int gthr   = r & 7;                 // 0..7
    const int g0     = gthr * 8;              // 8 gate cols = 2 hidden units
    const int b_glob = bg * 16 + b_loc;

    // load Wh' slice: w_s[k][f] = Whp[k][64*cg + f]
    for (int i = tid; i < 512 * 16; i += 256) {
        int k = i >> 4, f4 = (i & 15) * 4;
        *(float4*)(w_s + k * 64 + f4) =
            *(const float4*)(Whp + (size_t)k * G_ + 64 * cg + f4);
    }
    // zero h_s (t = 0 state)
    for (int i = tid; i < 16 * HS_; i += 256) h_s[i] = 0.f;

    float c0 = 0.f, c1 = 0.f;                 // register cell state (q==0 threads)
    __syncthreads();

    for (int t = 0; t < T_; t++) {
        // ---- stage this bg's 16 rows of h (32 KB), padded rows ----
        if (t > 0) {
            const float4* src = (const float4*)(g_hbuf + (size_t)(t & 1) * B_ * H_
                                                + (size_t)bg * 16 * H_);
            for (int i = tid; i < 2048; i += 256) {
                int row = i >> 7, c4 = i & 127;
                *(float4*)(h_s + row * HS_ + c4 * 4) = __ldcg(src + row * 128 + c4);
            }
        }
        // ---- prefetch xw' (q==0 only; consumed after reduction) ----
        float4 x0, x1;
        if (q == 0) {
            const float* xp = xw + (size_t)(b_glob * T_ + t) * G_ + cg * 64 + g0;
            x0 = __ldg((const float4*)xp);
            x1 = __ldg((const float4*)(xp + 4));
        }
        __syncthreads();

        // ---- z partial: 8 gate cols x 1 batch, K-half ----
        ull acc0 = 0ull, acc1 = 0ull, acc2 = 0ull, acc3 = 0ull;
        const float* hp = h_s + b_loc * HS_ + q * 256;
        const float* wp = w_s + (q * 256) * 64 + g0;
#pragma unroll 4
        for (int k4 = 0; k4 < 64; k4++) {
            float4 hv = *(const float4*)(hp + k4 * 4);
            const float* wr = wp + (k4 * 4) * 64;
            ull hh; ulonglong2 wa, wb;

            hh = pack2(hv.x, hv.x);
            wa = *(const ulonglong2*)(wr);
            wb = *(const ulonglong2*)(wr + 4);
            ffma2(acc0, hh, wa.x); ffma2(acc1, hh, wa.y);
            ffma2(acc2, hh, wb.x); ffma2(acc3, hh, wb.y);

            hh = pack2(hv.y, hv.y);
            wa = *(const ulonglong2*)(wr + 64);
            wb = *(const ulonglong2*)(wr + 68);
            ffma2(acc0, hh, wa.x); ffma2(acc1, hh, wa.y);
            ffma2(acc2, hh, wb.x); ffma2(acc3, hh, wb.y);

            hh = pack2(hv.z, hv.z);
            wa = *(const ulonglong2*)(wr + 128);
            wb = *(const ulonglong2*)(wr + 132);
            ffma2(acc0, hh, wa.x); ffma2(acc1, hh, wa.y);
            ffma2(acc2, hh, wb.x); ffma2(acc3, hh, wb.y);

            hh = pack2(hv.w, hv.w);
            wa = *(const ulonglong2*)(wr + 192);
            wb = *(const ulonglong2*)(wr + 196);
            ffma2(acc0, hh, wa.x); ffma2(acc1, hh, wa.y);
            ffma2(acc2, hh, wb.x); ffma2(acc3, hh, wb.y);
        }

        // ---- k-split reduction ----
        if (q) {
            ull* rp = red + r * 4;
            rp[0] = acc0; rp[1] = acc1; rp[2] = acc2; rp[3] = acc3;
        }
        __syncthreads();

        if (q == 0) {
            const ull* rp = red + r * 4;
            fadd2(acc0, rp[0]); fadd2(acc1, rp[1]);
            fadd2(acc2, rp[2]); fadd2(acc3, rp[3]);

            float z0, z1, z2, z3, z4, z5, z6, z7;
            unpack2(acc0, z0, z1); unpack2(acc1, z2, z3);
            unpack2(acc2, z4, z5); unpack2(acc3, z6, z7);
            z0 += x0.x; z1 += x0.y; z2 += x0.z; z3 += x0.w;
            z4 += x1.x; z5 += x1.y; z6 += x1.z; z7 += x1.w;

            // hidden j0: gates (i,f,g,o) = (z0,z1,z2,z3); hidden j0+1: (z4..z7)
            float ig0 = 1.f / (1.f + expf(-z0));
            float fg0 = 1.f / (1.f + expf(-z1));
            float gg0 = tanhf(z2);
            float og0 = 1.f / (1.f + expf(-z3));
            c0 = fmaf(fg0, c0, ig0 * gg0);
            float h0 = og0 * tanhf(c0);

            float ig1 = 1.f / (1.f + expf(-z4));
            float fg1 = 1.f / (1.f + expf(-z5));
            float gg1 = tanhf(z6);
            float og1 = 1.f / (1.f + expf(-z7));
            c1 = fmaf(fg1, c1, ig1 * gg1);
            float h1 = og1 * tanhf(c1);

            float* hdst = g_hbuf + (size_t)((t & 1) ^ 1) * B_ * H_;
            const int j0 = 16 * cg + gthr * 2;
            hdst[b_glob * H_ + j0]     = h0;
            hdst[b_glob * H_ + j0 + 1] = h1;
            if (hseqT) {
                hseqT[(size_t)j0 * M_ + b_glob * T_ + t]       = h0;
                hseqT[(size_t)(j0 + 1) * M_ + b_glob * T_ + t] = h1;
            }
        }
        __threadfence();
        group_barrier(bg);
    }
}

// ---------------- head (round-1 structure, h now [b][k]) ----------------
__global__ void __launch_bounds__(256) head_kernel(const float* __restrict__ Wd1,
                                                   const float* __restrict__ bd1,
                                                   const float* __restrict__ Wd2,
                                                   const float* __restrict__ bd2,
                                                   float* __restrict__ out)
{
    const int b = blockIdx.x;
    const int j = threadIdx.x;                 // 0..255
    const float* hfin = g_hbuf;                // final h in buf0, layout [b][k]
    float acc = 0.f;
#pragma unroll 8
    for (int k = 0; k < H_; k++)
        acc = fmaf(hfin[b * H_ + k], Wd1[k * (H_ / 2) + j], acc);
    float t1 = fmaxf(acc + bd1[j], 0.f);
    float p  = t1 * Wd2[j];
    __shared__ float s[256];
    s[j] = p;
    __syncthreads();
    for (int off = 128; off; off >>= 1) {
        if (j < off) s[j] += s[j + off];
        __syncthreads();
    }
    if (j == 0) out[b] = fmaxf(s[0] + bd2[0], 0.f);
}

// ---------------- launch ----------------
extern "C" void kernel_launch(void* const* d_in, const int* in_sizes, int n_in,
                              void* d_out, int out_size)
{
    (void)in_sizes; (void)n_in; (void)out_size;
    const float* x   = (const float*)d_in[0];
    const float* Wi1 = (const float*)d_in[2];
    const float* Wh1 = (const float*)d_in[3];
    const float* b1  = (const float*)d_in[4];
    const float* Wi2 = (const float*)d_in[5];
    const float* Wh2 = (const float*)d_in[6];
    const float* b2  = (const float*)d_in[7];
    const float* Wd1 = (const float*)d_in[8];
    const float* bd1 = (const float*)d_in[9];
    const float* Wd2 = (const float*)d_in[10];
    const float* bd2 = (const float*)d_in[11];
    float* out = (float*)d_out;

    float *xT, *xwb, *hseqT, *Wi1p, *Wi2p, *Wh1p, *Wh2p, *b1p, *b2p;
    cudaGetSymbolAddress((void**)&xT,    g_xT);
    cudaGetSymbolAddress((void**)&xwb,   g_xw);
    cudaGetSymbolAddress((void**)&hseqT, g_hseqT);
    cudaGetSymbolAddress((void**)&Wi1p,  g_Wi1p);
    cudaGetSymbolAddress((void**)&Wi2p,  g_Wi2p);
    cudaGetSymbolAddress((void**)&Wh1p,  g_Wh1p);
    cudaGetSymbolAddress((void**)&Wh2p,  g_Wh2p);
    cudaGetSymbolAddress((void**)&b1p,   g_b1p);
    cudaGetSymbolAddress((void**)&b2p,   g_b2p);

    const size_t smem = (32768 + 8320) * sizeof(float) + 4096;   // 168448 B
    cudaFuncSetAttribute(lstm_persistent,
                         cudaFuncAttributeMaxDynamicSharedMemorySize, (int)smem);

    // gate-interleaved weight/bias permutation (idempotent, in-graph)
    reorder_cols<<<(F_ * G_ + 255) / 256, 256>>>(Wi1, Wi1p, F_);
    reorder_cols<<<(H_ * G_ + 255) / 256, 256>>>(Wh1, Wh1p, H_);
    reorder_cols<<<(H_ * G_ + 255) / 256, 256>>>(Wi2, Wi2p, H_);
    reorder_cols<<<(H_ * G_ + 255) / 256, 256>>>(Wh2, Wh2p, H_);
    reorder_bias<<<G_ / 256, 256>>>(b1, b1p);
    reorder_bias<<<G_ / 256, 256>>>(b2, b2p);

    transpose_x<<<dim3(1024, 2), dim3(32, 8)>>>(x, xT);
    gemm_atb<<<dim3(G_ / 64, M_ / 64), 256>>>(xT, Wi1p, b1p, xwb, M_, G_, F_);
    lstm_persistent<<<NCTA_, 256, smem>>>(xwb, Wh1p, hseqT);
    gemm_atb<<<dim3(G_ / 64, M_ / 64), 256>>>(hseqT, Wi2p, b2p, xwb, M_, G_, H_);
    lstm_persistent<<<NCTA_, 256, smem>>>(xwb, Wh2p, nullptr);
    head_kernel<<<B_, 256>>>(Wd1, bd1, Wd2, bd2, out);
}

// round 6
// speedup vs baseline: 2.0743x; 2.0743x over previous
#include <cuda_runtime.h>
#include <math.h>

#define B_    64
#define T_    512
#define F_    64
#define H_    512
#define G_    2048          // 4*H
#define M_    (B_*T_)       // 32768
#define NCTA_ 128

typedef unsigned long long ull;

// ---------------- packed f32x2 helpers (validated round 4) ----------------
__device__ __forceinline__ void ffma2(ull& acc, ull a, ull b) {
    asm("fma.rn.f32x2 %0, %1, %2, %0;" : "+l"(acc) : "l"(a), "l"(b));
}
__device__ __forceinline__ ull pack2(float lo, float hi) {
    ull r; asm("mov.b64 %0, {%1, %2};" : "=l"(r) : "f"(lo), "f"(hi)); return r;
}
__device__ __forceinline__ void unpack2(ull v, float& lo, float& hi) {
    asm("mov.b64 {%0, %1}, %2;" : "=f"(lo), "=f"(hi) : "l"(v));
}

// ---------------- scratch (static device allocations only) ----------------
__device__ float g_xT[(size_t)F_ * M_];       //   8 MB : x transposed [F][M]
__device__ float g_xw[(size_t)M_ * G_];       // 256 MB : xW (+bias) [M][G], reused by both layers
__device__ float g_hseqT[(size_t)H_ * M_];    //  64 MB : layer-1 output transposed [H][M]
__device__ float g_hbufT[2 * H_ * B_];        // double-buffered h state, transposed [H][B]
__device__ unsigned g_cnt8[8 * 32];           // arrival counters, one per 128-B line
__device__ unsigned g_gen8[8 * 32];           // replicated generation words
__device__ unsigned g_done8;

// acquire load (plain load — same-address polls broadcast, no L2 serialization)
__device__ __forceinline__ unsigned ld_acq(const unsigned* p) {
    unsigned v;
    asm volatile("ld.acquire.gpu.global.u32 %0, [%1];" : "=r"(v) : "l"(p));
    return v;
}

// ---------------- grid-wide barrier: sharded arrivals + load-poll release ----------------
__device__ __forceinline__ void grid_barrier()
{
    __syncthreads();
    if (threadIdx.x == 0) {
        const unsigned lane = blockIdx.x & 7u;          // 16 CTAs per lane
        unsigned* cntp = &g_cnt8[lane * 32];
        unsigned* genp = &g_gen8[lane * 32];
        __threadfence();
        unsigned gen = ld_acq(genp);
        unsigned arrived = atomicAdd(cntp, 1u);
        if (arrived == 15u) {                            // lane closer
            atomicExch(cntp, 0u);
            unsigned d = atomicAdd(&g_done8, 1u);
            if (d == 7u) {                               // final closer: release all
                atomicExch(&g_done8, 0u);
                __threadfence();
#pragma unroll
                for (int l = 0; l < 8; l++)
                    atomicAdd(&g_gen8[l * 32], 1u);
            } else {
                while (ld_acq(genp) == gen) { __nanosleep(32); }
            }
        } else {
            while (ld_acq(genp) == gen) { __nanosleep(32); }
        }
        __threadfence();
    }
    __syncthreads();
}

// ---------------- x transpose: x[M][F] -> xT[F][M] ----------------
__global__ void __launch_bounds__(256) transpose_x(const float* __restrict__ x,
                                                   float* __restrict__ xT)
{
    __shared__ float tile[32][33];
    const int m0 = blockIdx.x * 32;
    const int f0 = blockIdx.y * 32;
    const int tx = threadIdx.x, ty = threadIdx.y;
#pragma unroll
    for (int i = 0; i < 32; i += 8)
        tile[ty + i][tx] = x[(size_t)(m0 + ty + i) * F_ + f0 + tx];
    __syncthreads();
#pragma unroll
    for (int i = 0; i < 32; i += 8)
        xT[(size_t)(f0 + ty + i) * M_ + m0 + tx] = tile[tx][ty + i];
}

// ---------------- GEMM (round-4 verbatim, proven) ----------------
__global__ void __launch_bounds__(256) gemm_atb(const float* __restrict__ AT,
                                                const float* __restrict__ Bm,
                                                const float* __restrict__ bias,
                                                float* __restrict__ C,
                                                int M, int N, int K)
{
    __shared__ float As[2][16 * 64];
    __shared__ float Bs[2][16 * 64];
    const int tid = threadIdx.x;
    const int tx = tid & 15, ty = tid >> 4;
    const int m0 = blockIdx.y * 64, n0 = blockIdx.x * 64;
    const int lr = tid >> 4, lc4 = (tid & 15) * 4;

    const float* ap = AT + (size_t)lr * M + m0 + lc4;
    const float* bp = Bm + (size_t)lr * N + n0 + lc4;
    float4 aReg = *(const float4*)ap;
    float4 bReg = *(const float4*)bp;

    ull accP[4][2];
#pragma unroll
    for (int i = 0; i < 4; i++) { accP[i][0] = 0ull; accP[i][1] = 0ull; }

    const int NT = K >> 4;
    for (int kt = 0; kt < NT; kt++) {
        const int cur = kt & 1;
        *(float4*)&As[cur][lr * 64 + lc4] = aReg;
        *(float4*)&Bs[cur][lr * 64 + lc4] = bReg;
        __syncthreads();
        if (kt + 1 < NT) {
            aReg = *(const float4*)(ap + (size_t)(kt + 1) * 16 * M);
            bReg = *(const float4*)(bp + (size_t)(kt + 1) * 16 * N);
        }
#pragma unroll
        for (int kk = 0; kk < 16; kk++) {
            float4 a = *(const float4*)&As[cur][kk * 64 + ty * 4];
            ulonglong2 bv = *(const ulonglong2*)&Bs[cur][kk * 64 + tx * 4];
            ull a0 = pack2(a.x, a.x);
            ull a1 = pack2(a.y, a.y);
            ull a2 = pack2(a.z, a.z);
            ull a3 = pack2(a.w, a.w);
            ffma2(accP[0][0], a0, bv.x); ffma2(accP[0][1], a0, bv.y);
            ffma2(accP[1][0], a1, bv.x); ffma2(accP[1][1], a1, bv.y);
            ffma2(accP[2][0], a2, bv.x); ffma2(accP[2][1], a2, bv.y);
            ffma2(accP[3][0], a3, bv.x); ffma2(accP[3][1], a3, bv.y);
        }
    }
    float acc[4][4];
#pragma unroll
    for (int i = 0; i < 4; i++) {
        unpack2(accP[i][0], acc[i][0], acc[i][1]);
        unpack2(accP[i][1], acc[i][2], acc[i][3]);
    }
    float4 bv = *(const float4*)(bias + n0 + tx * 4);
#pragma unroll
    for (int i = 0; i < 4; i++) {
        float4 o;
        o.x = acc[i][0] + bv.x;
        o.y = acc[i][1] + bv.y;
        o.z = acc[i][2] + bv.z;
        o.w = acc[i][3] + bv.w;
        *(float4*)&C[(size_t)(m0 + ty * 4 + i) * N + n0 + tx * 4] = o;
    }
}

// ---------------- persistent LSTM layer (round-4 structure) ----------------
// 128 CTAs, each owns 4 hidden cols (16 gate cols). z = xw[:,t,:] + h@Wh.
// SMEM: h_s[512][64] staged per step (__ldcg), w_s[512][16] loaded once, c persistent.
__global__ void __launch_bounds__(256, 1) lstm_persistent(const float* __restrict__ xw,
                                                          const float* __restrict__ Wh,
                                                          float* __restrict__ hseqT)
{
    extern __shared__ float sm[];
    float* h_s = sm;                 // 512*64 = 32768
    float* w_s = sm + 32768;         // 512*16 =  8192
    float* red = w_s + 8192;         // 3*64*16 = 3072
    float* z_s = red + 3072;         // 64*16  =  1024
    float* c_s = z_s + 1024;         // 64*4   =   256

    const int tid = threadIdx.x;
    const int hc0 = blockIdx.x * 4;

    // load Wh slice: w_s[k][g*4+c] = Wh[k][g*512 + hc0 + c]
    for (int i = tid; i < 512 * 4; i += 256) {
        int k = i >> 2, g = i & 3;
        *(float4*)(w_s + k * 16 + g * 4) =
            *(const float4*)(Wh + (size_t)k * G_ + g * H_ + hc0);
    }
    c_s[tid] = 0.f;
    {   // zero h buf0 (this CTA's slice)
        int c = tid >> 6, b = tid & 63;
        g_hbufT[(hc0 + c) * B_ + b] = 0.f;
    }
    __threadfence();
    grid_barrier();

    const int q  = tid >> 6;   // k-split group (K range [q*128, q*128+128))
    const int r  = tid & 63;
    const int rg = r & 15;     // batch rows 4*rg .. 4*rg+3
    const int cg = r >> 4;     // gate index 0..3 (tile cols 4*cg..4*cg+3)

    for (int t = 0; t < T_; t++) {
        const float* hsrc = g_hbufT + (t & 1) * (H_ * B_);
        float*       hdst = g_hbufT + ((t & 1) ^ 1) * (H_ * B_);

        // prefetch xw first (DRAM latency; q==0 threads only)
        float4 xv0, xv1, xv2, xv3;
        if (q == 0) {
            const float* xp = xw + (size_t)(4 * rg * T_ + t) * G_ + cg * H_ + hc0;
            xv0 = *(const float4*)(xp);
            xv1 = *(const float4*)(xp + (size_t)T_ * G_);
            xv2 = *(const float4*)(xp + (size_t)2 * T_ * G_);
            xv3 = *(const float4*)(xp + (size_t)3 * T_ * G_);
        }

        // stage full h (transposed: h_s[k][b]) from L2, bypassing L1
        for (int i = tid; i < (H_ * B_) / 4; i += 256)
            ((float4*)h_s)[i] = __ldcg((const float4*)hsrc + i);
        __syncthreads();

        ull accP[4][2];
#pragma unroll
        for (int i = 0; i < 4; i++) { accP[i][0] = 0ull; accP[i][1] = 0ull; }

        const float* hp = h_s + q * 128 * 64 + 4 * rg;
        const float* wp = w_s + q * 128 * 16 + 4 * cg;
#pragma unroll 8
        for (int kk = 0; kk < 128; kk++) {
            float4 hv = *(const float4*)(hp + kk * 64);
            ulonglong2 wv = *(const ulonglong2*)(wp + kk * 16);
            ull h0 = pack2(hv.x, hv.x);
            ull h1 = pack2(hv.y, hv.y);
            ull h2 = pack2(hv.z, hv.z);
            ull h3 = pack2(hv.w, hv.w);
            ffma2(accP[0][0], h0, wv.x); ffma2(accP[0][1], h0, wv.y);
            ffma2(accP[1][0], h1, wv.x); ffma2(accP[1][1], h1, wv.y);
            ffma2(accP[2][0], h2, wv.x); ffma2(accP[2][1], h2, wv.y);
            ffma2(accP[3][0], h3, wv.x); ffma2(accP[3][1], h3, wv.y);
        }

        float acc[4][4];
#pragma unroll
        for (int i = 0; i < 4; i++) {
            unpack2(accP[i][0], acc[i][0], acc[i][1]);
            unpack2(accP[i][1], acc[i][2], acc[i][3]);
        }

        if (q) {
            float* rp = red + ((q - 1) * 64 + r) * 16;
#pragma unroll
            for (int i = 0; i < 4; i++)
#pragma unroll
                for (int j = 0; j < 4; j++) rp[i * 4 + j] = acc[i][j];
        }
        __syncthreads();

        if (q == 0) {
#pragma unroll
            for (int qq = 0; qq < 3; qq++) {
                const float* rp = red + (qq * 64 + r) * 16;
#pragma unroll
                for (int i = 0; i < 4; i++)
#pragma unroll
                    for (int j = 0; j < 4; j++) acc[i][j] += rp[i * 4 + j];
            }
            float4 xv[4] = {xv0, xv1, xv2, xv3};
#pragma unroll
            for (int i = 0; i < 4; i++) {
                const float* xf = (const float*)&xv[i];
#pragma unroll
                for (int j = 0; j < 4; j++)
                    z_s[(4 * rg + i) * 16 + 4 * cg + j] = acc[i][j] + xf[j];
            }
        }
        __syncthreads();

        // state update: thread -> (b = tid>>2, c = tid&3)
        {
            const int b = tid >> 2, c = tid & 3;
            float zi = z_s[b * 16 + 0  + c];
            float zf = z_s[b * 16 + 4  + c];
            float zg = z_s[b * 16 + 8  + c];
            float zo = z_s[b * 16 + 12 + c];
            float ig = 1.f / (1.f + expf(-zi));
            float fg = 1.f / (1.f + expf(-zf));
            float gg = tanhf(zg);
            float og = 1.f / (1.f + expf(-zo));
            float cc = fmaf(fg, c_s[tid], ig * gg);
            c_s[tid] = cc;
            float hh = og * tanhf(cc);
            hdst[(hc0 + c) * B_ + b] = hh;
            if (hseqT)
                hseqT[(size_t)(hc0 + c) * M_ + b * T_ + t] = hh;
        }
        __threadfence();
        grid_barrier();
    }
}

// ---------------- head: out[b] = relu(relu(h@Wd1 + bd1) @ Wd2 + bd2) ----------------
__global__ void __launch_bounds__(256) head_kernel(const float* __restrict__ Wd1,
                                                   const float* __restrict__ bd1,
                                                   const float* __restrict__ Wd2,
                                                   const float* __restrict__ bd2,
                                                   float* __restrict__ out)
{
    const int b = blockIdx.x;
    const int j = threadIdx.x;                 // 0..255
    const float* hT = g_hbufT;                 // final h lives in buf0 (t=511 writes buf0)
    float acc = 0.f;
#pragma unroll 8
    for (int k = 0; k < H_; k++)
        acc = fmaf(hT[k * B_ + b], Wd1[k * (H_ / 2) + j], acc);
    float t1 = fmaxf(acc + bd1[j], 0.f);
    float p  = t1 * Wd2[j];
    __shared__ float s[256];
    s[j] = p;
    __syncthreads();
    for (int off = 128; off; off >>= 1) {
        if (j < off) s[j] += s[j + off];
        __syncthreads();
    }
    if (j == 0) out[b] = fmaxf(s[0] + bd2[0], 0.f);
}

// ---------------- launch ----------------
extern "C" void kernel_launch(void* const* d_in, const int* in_sizes, int n_in,
                              void* d_out, int out_size)
{
    (void)in_sizes; (void)n_in; (void)out_size;
    const float* x   = (const float*)d_in[0];
    // d_in[1] = training (unused)
    const float* Wi1 = (const float*)d_in[2];
    const float* Wh1 = (const float*)d_in[3];
    const float* b1  = (const float*)d_in[4];
    const float* Wi2 = (const float*)d_in[5];
    const float* Wh2 = (const float*)d_in[6];
    const float* b2  = (const float*)d_in[7];
    const float* Wd1 = (const float*)d_in[8];
    const float* bd1 = (const float*)d_in[9];
    const float* Wd2 = (const float*)d_in[10];
    const float* bd2 = (const float*)d_in[11];
    float* out = (float*)d_out;

    float *xT, *xwb, *hseqT;
    cudaGetSymbolAddress((void**)&xT,    g_xT);
    cudaGetSymbolAddress((void**)&xwb,   g_xw);
    cudaGetSymbolAddress((void**)&hseqT, g_hseqT);

    const size_t smem = (32768 + 8192 + 3072 + 1024 + 256) * sizeof(float); // 181248 B
    cudaFuncSetAttribute(lstm_persistent,
                         cudaFuncAttributeMaxDynamicSharedMemorySize, (int)smem);

    transpose_x<<<dim3(1024, 2), dim3(32, 8)>>>(x, xT);
    gemm_atb<<<dim3(G_ / 64, M_ / 64), 256>>>(xT, Wi1, b1, xwb, M_, G_, F_);
    lstm_persistent<<<NCTA_, 256, smem>>>(xwb, Wh1, hseqT);
    gemm_atb<<<dim3(G_ / 64, M_ / 64), 256>>>(hseqT, Wi2, b2, xwb, M_, G_, H_);
    lstm_persistent<<<NCTA_, 256, smem>>>(xwb, Wh2, nullptr);
    head_kernel<<<B_, 256>>>(Wd1, bd1, Wd2, bd2, out);
}

// round 7
// speedup vs baseline: 2.2300x; 1.0751x over previous
#include <cuda_runtime.h>
#include <math.h>

#define B_    64
#define T_    512
#define F_    64
#define H_    512
#define G_    2048          // 4*H
#define M_    (B_*T_)       // 32768
#define NCTA_ 128

typedef unsigned long long ull;

// ---------------- packed f32x2 helpers (validated round 4) ----------------
__device__ __forceinline__ void ffma2(ull& acc, ull a, ull b) {
    asm("fma.rn.f32x2 %0, %1, %2, %0;" : "+l"(acc) : "l"(a), "l"(b));
}
__device__ __forceinline__ ull pack2(float lo, float hi) {
    ull r; asm("mov.b64 %0, {%1, %2};" : "=l"(r) : "f"(lo), "f"(hi)); return r;
}
__device__ __forceinline__ void unpack2(ull v, float& lo, float& hi) {
    asm("mov.b64 {%0, %1}, %2;" : "=f"(lo), "=f"(hi) : "l"(v));
}

// ---------------- cp.async helpers ----------------
__device__ __forceinline__ void cp_async16(float* smem_dst, const float4* gsrc) {
    unsigned s = (unsigned)__cvta_generic_to_shared(smem_dst);
    asm volatile("cp.async.cg.shared.global [%0], [%1], 16;" :: "r"(s), "l"(gsrc));
}
__device__ __forceinline__ void cp_commit() {
    asm volatile("cp.async.commit_group;");
}
template <int N>
__device__ __forceinline__ void cp_wait() {
    asm volatile("cp.async.wait_group %0;" :: "n"(N));
}

// ---------------- scratch (static device allocations only) ----------------
__device__ float g_xT[(size_t)F_ * M_];       //   8 MB : x transposed [F][M]
__device__ float g_xw[(size_t)M_ * G_];       // 256 MB : xW (+bias) [M][G], reused by both layers
__device__ float g_hseqT[(size_t)H_ * M_];    //  64 MB : layer-1 output transposed [H][M]
__device__ float g_hbufT[2 * H_ * B_];        // double-buffered h state, transposed [H][B]
__device__ unsigned g_cnt8[8 * 32];           // arrival counters, one per 128-B line
__device__ unsigned g_gen8[8 * 32];           // replicated generation words
__device__ unsigned g_done8;

// acquire load (plain load — same-address polls broadcast, no L2 serialization)
__device__ __forceinline__ unsigned ld_acq(const unsigned* p) {
    unsigned v;
    asm volatile("ld.acquire.gpu.global.u32 %0, [%1];" : "=r"(v) : "l"(p));
    return v;
}

// ---------------- grid-wide barrier: sharded arrivals + load-poll release ----------------
__device__ __forceinline__ void grid_barrier()
{
    __syncthreads();
    if (threadIdx.x == 0) {
        const unsigned lane = blockIdx.x & 7u;          // 16 CTAs per lane
        unsigned* cntp = &g_cnt8[lane * 32];
        unsigned* genp = &g_gen8[lane * 32];
        __threadfence();
        unsigned gen = ld_acq(genp);
        unsigned arrived = atomicAdd(cntp, 1u);
        if (arrived == 15u) {                            // lane closer
            atomicExch(cntp, 0u);
            unsigned d = atomicAdd(&g_done8, 1u);
            if (d == 7u) {                               // final closer: release all
                atomicExch(&g_done8, 0u);
                __threadfence();
#pragma unroll
                for (int l = 0; l < 8; l++)
                    atomicAdd(&g_gen8[l * 32], 1u);
            } else {
                while (ld_acq(genp) == gen) { __nanosleep(32); }
            }
        } else {
            while (ld_acq(genp) == gen) { __nanosleep(32); }
        }
        __threadfence();
    }
    __syncthreads();
}

// ---------------- x transpose: x[M][F] -> xT[F][M] ----------------
__global__ void __launch_bounds__(256) transpose_x(const float* __restrict__ x,
                                                   float* __restrict__ xT)
{
    __shared__ float tile[32][33];
    const int m0 = blockIdx.x * 32;
    const int f0 = blockIdx.y * 32;
    const int tx = threadIdx.x, ty = threadIdx.y;
#pragma unroll
    for (int i = 0; i < 32; i += 8)
        tile[ty + i][tx] = x[(size_t)(m0 + ty + i) * F_ + f0 + tx];
    __syncthreads();
#pragma unroll
    for (int i = 0; i < 32; i += 8)
        xT[(size_t)(f0 + ty + i) * M_ + m0 + tx] = tile[tx][ty + i];
}

// ---------------- GEMM (round-4 verbatim, proven) ----------------
__global__ void __launch_bounds__(256) gemm_atb(const float* __restrict__ AT,
                                                const float* __restrict__ Bm,
                                                const float* __restrict__ bias,
                                                float* __restrict__ C,
                                                int M, int N, int K)
{
    __shared__ float As[2][16 * 64];
    __shared__ float Bs[2][16 * 64];
    const int tid = threadIdx.x;
    const int tx = tid & 15, ty = tid >> 4;
    const int m0 = blockIdx.y * 64, n0 = blockIdx.x * 64;
    const int lr = tid >> 4, lc4 = (tid & 15) * 4;

    const float* ap = AT + (size_t)lr * M + m0 + lc4;
    const float* bp = Bm + (size_t)lr * N + n0 + lc4;
    float4 aReg = *(const float4*)ap;
    float4 bReg = *(const float4*)bp;

    ull accP[4][2];
#pragma unroll
    for (int i = 0; i < 4; i++) { accP[i][0] = 0ull; accP[i][1] = 0ull; }

    const int NT = K >> 4;
    for (int kt = 0; kt < NT; kt++) {
        const int cur = kt & 1;
        *(float4*)&As[cur][lr * 64 + lc4] = aReg;
        *(float4*)&Bs[cur][lr * 64 + lc4] = bReg;
        __syncthreads();
        if (kt + 1 < NT) {
            aReg = *(const float4*)(ap + (size_t)(kt + 1) * 16 * M);
            bReg = *(const float4*)(bp + (size_t)(kt + 1) * 16 * N);
        }
#pragma unroll
        for (int kk = 0; kk < 16; kk++) {
            float4 a = *(const float4*)&As[cur][kk * 64 + ty * 4];
            ulonglong2 bv = *(const ulonglong2*)&Bs[cur][kk * 64 + tx * 4];
            ull a0 = pack2(a.x, a.x);
            ull a1 = pack2(a.y, a.y);
            ull a2 = pack2(a.z, a.z);
            ull a3 = pack2(a.w, a.w);
            ffma2(accP[0][0], a0, bv.x); ffma2(accP[0][1], a0, bv.y);
            ffma2(accP[1][0], a1, bv.x); ffma2(accP[1][1], a1, bv.y);
            ffma2(accP[2][0], a2, bv.x); ffma2(accP[2][1], a2, bv.y);
            ffma2(accP[3][0], a3, bv.x); ffma2(accP[3][1], a3, bv.y);
        }
    }
    float acc[4][4];
#pragma unroll
    for (int i = 0; i < 4; i++) {
        unpack2(accP[i][0], acc[i][0], acc[i][1]);
        unpack2(accP[i][1], acc[i][2], acc[i][3]);
    }
    float4 bv = *(const float4*)(bias + n0 + tx * 4);
#pragma unroll
    for (int i = 0; i < 4; i++) {
        float4 o;
        o.x = acc[i][0] + bv.x;
        o.y = acc[i][1] + bv.y;
        o.z = acc[i][2] + bv.z;
        o.w = acc[i][3] + bv.w;
        *(float4*)&C[(size_t)(m0 + ty * 4 + i) * N + n0 + tx * 4] = o;
    }
}

// ---------------- persistent LSTM layer (round-6 + cp.async staging pipeline) ----------------
// 128 CTAs, each owns 4 hidden cols (16 gate cols). z = xw[:,t,:] + h@Wh.
// h staged in 4 chunks of 128 K-rows via cp.async, overlapped with compute.
__global__ void __launch_bounds__(256, 1) lstm_persistent(const float* __restrict__ xw,
                                                          const float* __restrict__ Wh,
                                                          float* __restrict__ hseqT)
{
    extern __shared__ float sm[];
    float* h_s = sm;                 // 512*64 = 32768
    float* w_s = sm + 32768;         // 512*16 =  8192
    float* red = w_s + 8192;         // 3*64*16 = 3072
    float* z_s = red + 3072;         // 64*16  =  1024
    float* c_s = z_s + 1024;         // 64*4   =   256

    const int tid = threadIdx.x;
    const int hc0 = blockIdx.x * 4;

    // load Wh slice: w_s[k][g*4+c] = Wh[k][g*512 + hc0 + c]
    for (int i = tid; i < 512 * 4; i += 256) {
        int k = i >> 2, g = i & 3;
        *(float4*)(w_s + k * 16 + g * 4) =
            *(const float4*)(Wh + (size_t)k * G_ + g * H_ + hc0);
    }
    c_s[tid] = 0.f;
    {   // zero h buf0 (this CTA's slice)
        int c = tid >> 6, b = tid & 63;
        g_hbufT[(hc0 + c) * B_ + b] = 0.f;
    }
    __threadfence();
    grid_barrier();

    const int q  = tid >> 6;   // k-split group
    const int r  = tid & 63;
    const int rg = r & 15;     // batch rows 4*rg .. 4*rg+3
    const int cg = r >> 4;     // gate index 0..3 (tile cols 4*cg..4*cg+3)

    for (int t = 0; t < T_; t++) {
        const float* hsrc = g_hbufT + (t & 1) * (H_ * B_);
        float*       hdst = g_hbufT + ((t & 1) ^ 1) * (H_ * B_);
        const float4* hsrc4 = (const float4*)hsrc;

        // prefetch xw first (DRAM latency; q==0 threads only)
        float4 xv0, xv1, xv2, xv3;
        if (q == 0) {
            const float* xp = xw + (size_t)(4 * rg * T_ + t) * G_ + cg * H_ + hc0;
            xv0 = *(const float4*)(xp);
            xv1 = *(const float4*)(xp + (size_t)T_ * G_);
            xv2 = *(const float4*)(xp + (size_t)2 * T_ * G_);
            xv3 = *(const float4*)(xp + (size_t)3 * T_ * G_);
        }

        // issue chunk 0 (k rows [0,128) = float4 idx [0,2048))
#pragma unroll
        for (int j = 0; j < 8; j++) {
            int idx = tid + j * 256;
            cp_async16(h_s + idx * 4, hsrc4 + idx);
        }
        cp_commit();

        ull accP[4][2];
#pragma unroll
        for (int i = 0; i < 4; i++) { accP[i][0] = 0ull; accP[i][1] = 0ull; }

#pragma unroll
        for (int c = 0; c < 4; c++) {
            if (c < 3) {
                // issue chunk c+1, then wait for chunk c (allow 1 group in flight)
#pragma unroll
                for (int j = 0; j < 8; j++) {
                    int idx = (c + 1) * 2048 + tid + j * 256;
                    cp_async16(h_s + idx * 4, hsrc4 + idx);
                }
                cp_commit();
                cp_wait<1>();
            } else {
                cp_wait<0>();
            }
            __syncthreads();

            // compute chunk c: k in [c*128 + q*32, c*128 + q*32 + 32)
            const float* hp = h_s + (c * 128 + q * 32) * 64 + 4 * rg;
            const float* wp = w_s + (c * 128 + q * 32) * 16 + 4 * cg;
#pragma unroll 8
            for (int kk = 0; kk < 32; kk++) {
                float4 hv = *(const float4*)(hp + kk * 64);
                ulonglong2 wv = *(const ulonglong2*)(wp + kk * 16);
                ull h0 = pack2(hv.x, hv.x);
                ull h1 = pack2(hv.y, hv.y);
                ull h2 = pack2(hv.z, hv.z);
                ull h3 = pack2(hv.w, hv.w);
                ffma2(accP[0][0], h0, wv.x); ffma2(accP[0][1], h0, wv.y);
                ffma2(accP[1][0], h1, wv.x); ffma2(accP[1][1], h1, wv.y);
                ffma2(accP[2][0], h2, wv.x); ffma2(accP[2][1], h2, wv.y);
                ffma2(accP[3][0], h3, wv.x); ffma2(accP[3][1], h3, wv.y);
            }
        }

        float acc[4][4];
#pragma unroll
        for (int i = 0; i < 4; i++) {
            unpack2(accP[i][0], acc[i][0], acc[i][1]);
            unpack2(accP[i][1], acc[i][2], acc[i][3]);
        }

        if (q) {
            float* rp = red + ((q - 1) * 64 + r) * 16;
#pragma unroll
            for (int i = 0; i < 4; i++)
#pragma unroll
                for (int j = 0; j < 4; j++) rp[i * 4 + j] = acc[i][j];
        }
        __syncthreads();

        if (q == 0) {
#pragma unroll
            for (int qq = 0; qq < 3; qq++) {
                const float* rp = red + (qq * 64 + r) * 16;
#pragma unroll
                for (int i = 0; i < 4; i++)
#pragma unroll
                    for (int j = 0; j < 4; j++) acc[i][j] += rp[i * 4 + j];
            }
            float4 xv[4] = {xv0, xv1, xv2, xv3};
#pragma unroll
            for (int i = 0; i < 4; i++) {
                const float* xf = (const float*)&xv[i];
#pragma unroll
                for (int j = 0; j < 4; j++)
                    z_s[(4 * rg + i) * 16 + 4 * cg + j] = acc[i][j] + xf[j];
            }
        }
        __syncthreads();

        // state update: thread -> (b = tid>>2, c = tid&3)
        {
            const int b = tid >> 2, c = tid & 3;
            float zi = z_s[b * 16 + 0  + c];
            float zf = z_s[b * 16 + 4  + c];
            float zg = z_s[b * 16 + 8  + c];
            float zo = z_s[b * 16 + 12 + c];
            float ig = 1.f / (1.f + expf(-zi));
            float fg = 1.f / (1.f + expf(-zf));
            float gg = tanhf(zg);
            float og = 1.f / (1.f + expf(-zo));
            float cc = fmaf(fg, c_s[tid], ig * gg);
            c_s[tid] = cc;
            float hh = og * tanhf(cc);
            hdst[(hc0 + c) * B_ + b] = hh;
            if (hseqT)
                hseqT[(size_t)(hc0 + c) * M_ + b * T_ + t] = hh;
        }
        grid_barrier();   // barrier performs the release fence
    }
}

// ---------------- head: out[b] = relu(relu(h@Wd1 + bd1) @ Wd2 + bd2) ----------------
__global__ void __launch_bounds__(256) head_kernel(const float* __restrict__ Wd1,
                                                   const float* __restrict__ bd1,
                                                   const float* __restrict__ Wd2,
                                                   const float* __restrict__ bd2,
                                                   float* __restrict__ out)
{
    const int b = blockIdx.x;
    const int j = threadIdx.x;                 // 0..255
    const float* hT = g_hbufT;                 // final h lives in buf0 (t=511 writes buf0)
    float acc = 0.f;
#pragma unroll 8
    for (int k = 0; k < H_; k++)
        acc = fmaf(hT[k * B_ + b], Wd1[k * (H_ / 2) + j], acc);
    float t1 = fmaxf(acc + bd1[j], 0.f);
    float p  = t1 * Wd2[j];
    __shared__ float s[256];
    s[j] = p;
    __syncthreads();
    for (int off = 128; off; off >>= 1) {
        if (j < off) s[j] += s[j + off];
        __syncthreads();
    }
    if (j == 0) out[b] = fmaxf(s[0] + bd2[0], 0.f);
}

// ---------------- launch ----------------
extern "C" void kernel_launch(void* const* d_in, const int* in_sizes, int n_in,
                              void* d_out, int out_size)
{
    (void)in_sizes; (void)n_in; (void)out_size;
    const float* x   = (const float*)d_in[0];
    // d_in[1] = training (unused)
    const float* Wi1 = (const float*)d_in[2];
    const float* Wh1 = (const float*)d_in[3];
    const float* b1  = (const float*)d_in[4];
    const float* Wi2 = (const float*)d_in[5];
    const float* Wh2 = (const float*)d_in[6];
    const float* b2  = (const float*)d_in[7];
    const float* Wd1 = (const float*)d_in[8];
    const float* bd1 = (const float*)d_in[9];
    const float* Wd2 = (const float*)d_in[10];
    const float* bd2 = (const float*)d_in[11];
    float* out = (float*)d_out;

    float *xT, *xwb, *hseqT;
    cudaGetSymbolAddress((void**)&xT,    g_xT);
    cudaGetSymbolAddress((void**)&xwb,   g_xw);
    cudaGetSymbolAddress((void**)&hseqT, g_hseqT);

    const size_t smem = (32768 + 8192 + 3072 + 1024 + 256) * sizeof(float); // 181248 B
    cudaFuncSetAttribute(lstm_persistent,
                         cudaFuncAttributeMaxDynamicSharedMemorySize, (int)smem);

    transpose_x<<<dim3(1024, 2), dim3(32, 8)>>>(x, xT);
    gemm_atb<<<dim3(G_ / 64, M_ / 64), 256>>>(xT, Wi1, b1, xwb, M_, G_, F_);
    lstm_persistent<<<NCTA_, 256, smem>>>(xwb, Wh1, hseqT);
    gemm_atb<<<dim3(G_ / 64, M_ / 64), 256>>>(hseqT, Wi2, b2, xwb, M_, G_, H_);
    lstm_persistent<<<NCTA_, 256, smem>>>(xwb, Wh2, nullptr);
    head_kernel<<<B_, 256>>>(Wd1, bd1, Wd2, bd2, out);
}

// round 9
// speedup vs baseline: 2.5387x; 1.1384x over previous
#include <cuda_runtime.h>
#include <cuda_bf16.h>
#include <math.h>

#define B_    64
#define T_    512
#define F_    64
#define H_    512
#define G_    2048          // 4*H
#define M_    (B_*T_)       // 32768
#define NCTA_ 128

typedef unsigned long long ull;

// ---------------- packed f32x2 helpers (validated round 4) ----------------
__device__ __forceinline__ void ffma2(ull& acc, ull a, ull b) {
    asm("fma.rn.f32x2 %0, %1, %2, %0;" : "+l"(acc) : "l"(a), "l"(b));
}
__device__ __forceinline__ ull pack2(float lo, float hi) {
    ull r; asm("mov.b64 %0, {%1, %2};" : "=l"(r) : "f"(lo), "f"(hi)); return r;
}
__device__ __forceinline__ void unpack2(ull v, float& lo, float& hi) {
    asm("mov.b64 {%0, %1}, %2;" : "=f"(lo), "=f"(hi) : "l"(v));
}

// ---------------- cp.async helpers ----------------
__device__ __forceinline__ void cp_async16(void* smem_dst, const void* gsrc) {
    unsigned s = (unsigned)__cvta_generic_to_shared(smem_dst);
    asm volatile("cp.async.cg.shared.global [%0], [%1], 16;" :: "r"(s), "l"(gsrc));
}
__device__ __forceinline__ void cp_commit() {
    asm volatile("cp.async.commit_group;");
}
template <int N>
__device__ __forceinline__ void cp_wait() {
    asm volatile("cp.async.wait_group %0;" :: "n"(N));
}

// ---------------- HMMA (mma.sync) helpers — baseline PTX, sm_80+ ----------------
#define SWZ128(x) ((x) ^ (((x) >> 3) & 0x70))

__device__ __forceinline__ void ldsm_x4(unsigned& r0, unsigned& r1, unsigned& r2, unsigned& r3,
                                        unsigned addr) {
    asm volatile("ldmatrix.sync.aligned.m8n8.x4.shared.b16 {%0,%1,%2,%3}, [%4];"
                 : "=r"(r0), "=r"(r1), "=r"(r2), "=r"(r3) : "r"(addr));
}
__device__ __forceinline__ void ldsm_x2(unsigned& r0, unsigned& r1, unsigned addr) {
    asm volatile("ldmatrix.sync.aligned.m8n8.x2.shared.b16 {%0,%1}, [%2];"
                 : "=r"(r0), "=r"(r1) : "r"(addr));
}
__device__ __forceinline__ void mma_bf16(float* c, const unsigned* a, const unsigned* b) {
    asm volatile("mma.sync.aligned.m16n8k16.row.col.f32.bf16.bf16.f32 "
                 "{%0,%1,%2,%3}, {%4,%5,%6,%7}, {%8,%9}, {%0,%1,%2,%3};"
                 : "+f"(c[0]), "+f"(c[1]), "+f"(c[2]), "+f"(c[3])
                 : "r"(a[0]), "r"(a[1]), "r"(a[2]), "r"(a[3]), "r"(b[0]), "r"(b[1]));
}

// ---------------- scratch (static device allocations only) ----------------
__device__ float g_xT[(size_t)F_ * M_];       //   8 MB : x transposed [F][M]
__device__ float g_xw[(size_t)M_ * G_];       // 256 MB : xW (+bias) [M][G]
__device__ float g_hseq[(size_t)M_ * H_];     //  64 MB : layer-1 output [M][H] (row-major)
__device__ float g_hbufT[2 * H_ * B_];        // double-buffered h state, transposed [H][B]
__device__ __nv_bfloat16 g_Ahi[(size_t)M_ * H_];   // 32 MB split-bf16 of hseq
__device__ __nv_bfloat16 g_Alo[(size_t)M_ * H_];
__device__ __nv_bfloat16 g_Bhi[(size_t)G_ * H_];   // 2 MB : Wi2^T split-bf16 [N][K]
__device__ __nv_bfloat16 g_Blo[(size_t)G_ * H_];
__device__ unsigned g_cnt8[8 * 32];
__device__ unsigned g_gen8[8 * 32];
__device__ unsigned g_done8;

// acquire load (plain load — same-address polls broadcast, no L2 serialization)
__device__ __forceinline__ unsigned ld_acq(const unsigned* p) {
    unsigned v;
    asm volatile("ld.acquire.gpu.global.u32 %0, [%1];" : "=r"(v) : "l"(p));
    return v;
}

// ---------------- grid-wide barrier: sharded arrivals + load-poll release ----------------
__device__ __forceinline__ void grid_barrier()
{
    __syncthreads();
    if (threadIdx.x == 0) {
        const unsigned lane = blockIdx.x & 7u;          // 16 CTAs per lane
        unsigned* cntp = &g_cnt8[lane * 32];
        unsigned* genp = &g_gen8[lane * 32];
        __threadfence();
        unsigned gen = ld_acq(genp);
        unsigned arrived = atomicAdd(cntp, 1u);
        if (arrived == 15u) {                            // lane closer
            atomicExch(cntp, 0u);
            unsigned d = atomicAdd(&g_done8, 1u);
            if (d == 7u) {                               // final closer: release all
                atomicExch(&g_done8, 0u);
                __threadfence();
#pragma unroll
                for (int l = 0; l < 8; l++)
                    atomicAdd(&g_gen8[l * 32], 1u);
            } else {
                while (ld_acq(genp) == gen) { __nanosleep(32); }
            }
        } else {
            while (ld_acq(genp) == gen) { __nanosleep(32); }
        }
        __threadfence();
    }
    __syncthreads();
}

// ---------------- x transpose: x[M][F] -> xT[F][M] ----------------
__global__ void __launch_bounds__(256) transpose_x(const float* __restrict__ x,
                                                   float* __restrict__ xT)
{
    __shared__ float tile[32][33];
    const int m0 = blockIdx.x * 32;
    const int f0 = blockIdx.y * 32;
    const int tx = threadIdx.x, ty = threadIdx.y;
#pragma unroll
    for (int i = 0; i < 32; i += 8)
        tile[ty + i][tx] = x[(size_t)(m0 + ty + i) * F_ + f0 + tx];
    __syncthreads();
#pragma unroll
    for (int i = 0; i < 32; i += 8)
        xT[(size_t)(f0 + ty + i) * M_ + m0 + tx] = tile[tx][ty + i];
}

// ---------------- split-bf16 conversions ----------------
__global__ void __launch_bounds__(256) cvt_split(const float* __restrict__ src,
                                                 __nv_bfloat16* __restrict__ hi,
                                                 __nv_bfloat16* __restrict__ lo)
{
    size_t i = (size_t)blockIdx.x * 256 + threadIdx.x;
    float x = src[i];
    __nv_bfloat16 h = __float2bfloat16(x);
    hi[i] = h;
    lo[i] = __float2bfloat16(x - __bfloat162float(h));
}
// Bhi[n][k] = split(Wi2[k][n])
__global__ void __launch_bounds__(256) cvt_wi2t(const float* __restrict__ Wi2,
                                                __nv_bfloat16* __restrict__ hi,
                                                __nv_bfloat16* __restrict__ lo)
{
    int i = blockIdx.x * 256 + threadIdx.x;          // i over G_*H_
    int n = i >> 9, k = i & 511;
    float x = Wi2[(size_t)k * G_ + n];
    __nv_bfloat16 h = __float2bfloat16(x);
    hi[i] = h;
    lo[i] = __float2bfloat16(x - __bfloat162float(h));
}

// ---------------- GEMM (FFMA2, proven) — used for GEMM1 only ----------------
__global__ void __launch_bounds__(256) gemm_atb(const float* __restrict__ AT,
                                                const float* __restrict__ Bm,
                                                const float* __restrict__ bias,
                                                float* __restrict__ C,
                                                int M, int N, int K)
{
    __shared__ float As[2][16 * 64];
    __shared__ float Bs[2][16 * 64];
    const int tid = threadIdx.x;
    const int tx = tid & 15, ty = tid >> 4;
    const int m0 = blockIdx.y * 64, n0 = blockIdx.x * 64;
    const int lr = tid >> 4, lc4 = (tid & 15) * 4;

    const float* ap = AT + (size_t)lr * M + m0 + lc4;
    const float* bp = Bm + (size_t)lr * N + n0 + lc4;
    float4 aReg = *(const float4*)ap;
    float4 bReg = *(const float4*)bp;

    ull accP[4][2];
#pragma unroll
    for (int i = 0; i < 4; i++) { accP[i][0] = 0ull; accP[i][1] = 0ull; }

    const int NT = K >> 4;
    for (int kt = 0; kt < NT; kt++) {
        const int cur = kt & 1;
        *(float4*)&As[cur][lr * 64 + lc4] = aReg;
        *(float4*)&Bs[cur][lr * 64 + lc4] = bReg;
        __syncthreads();
        if (kt + 1 < NT) {
            aReg = *(const float4*)(ap + (size_t)(kt + 1) * 16 * M);
            bReg = *(const float4*)(bp + (size_t)(kt + 1) * 16 * N);
        }
#pragma unroll
        for (int kk = 0; kk < 16; kk++) {
            float4 a = *(const float4*)&As[cur][kk * 64 + ty * 4];
            ulonglong2 bv = *(const ulonglong2*)&Bs[cur][kk * 64 + tx * 4];
            ull a0 = pack2(a.x, a.x);
            ull a1 = pack2(a.y, a.y);
            ull a2 = pack2(a.z, a.z);
            ull a3 = pack2(a.w, a.w);
            ffma2(accP[0][0], a0, bv.x); ffma2(accP[0][1], a0, bv.y);
            ffma2(accP[1][0], a1, bv.x); ffma2(accP[1][1], a1, bv.y);
            ffma2(accP[2][0], a2, bv.x); ffma2(accP[2][1], a2, bv.y);
            ffma2(accP[3][0], a3, bv.x); ffma2(accP[3][1], a3, bv.y);
        }
    }
    float acc[4][4];
#pragma unroll
    for (int i = 0; i < 4; i++) {
        unpack2(accP[i][0], acc[i][0], acc[i][1]);
        unpack2(accP[i][1], acc[i][2], acc[i][3]);
    }
    float4 bv = *(const float4*)(bias + n0 + tx * 4);
#pragma unroll
    for (int i = 0; i < 4; i++) {
        float4 o;
        o.x = acc[i][0] + bv.x;
        o.y = acc[i][1] + bv.y;
        o.z = acc[i][2] + bv.z;
        o.w = acc[i][3] + bv.w;
        *(float4*)&C[(size_t)(m0 + ty * 4 + i) * N + n0 + tx * 4] = o;
    }
}

// ---------------- HMMA GEMM2: C[M][N] = A@Wi2 + bias, split-bf16 x3 ----------------
// Tile 128m x 128n per CTA, 8 warps (2m x 4n of 64x32 warp tiles), K=512 in 8 stages.
// A[m][k], B[n][k] bf16 hi/lo in global; smem stages SW128 (128B rows of 64 bf16).
__global__ void __launch_bounds__(256, 1) gemm_tc(const __nv_bfloat16* __restrict__ Ahi,
                                                  const __nv_bfloat16* __restrict__ Alo,
                                                  const __nv_bfloat16* __restrict__ Bhi,
                                                  const __nv_bfloat16* __restrict__ Blo,
                                                  const float* __restrict__ bias,
                                                  float* __restrict__ C)
{
    extern __shared__ char smc[];
    // layout: [128..640) bias, [1024 + s*65536) stages of {Ahi,Alo,Bhi,Blo} 16KB each
    float* bs = (float*)(smc + 128);
    const int tid = threadIdx.x;
    const int wid = tid >> 5, lane = tid & 31;
    const int m0 = blockIdx.y * 128, n0 = blockIdx.x * 128;
    const unsigned sbase = (unsigned)__cvta_generic_to_shared(smc);

    if (tid < 128) bs[tid] = bias[n0 + tid];

    const int mw = wid & 1;        // 64-row block
    const int nw = wid >> 1;       // 32-col block
    const int grp = lane >> 2, tig = lane & 3;

    // ldmatrix lane-address components
    const int aRow = lane & 15;                // A: m-row within 16
    const int aKof = (lane >> 4) << 3;         // A: k offset 0/8
    const int bRow = lane & 7;                 // B: n-row within 8
    const int bKof = ((lane >> 3) & 1) << 3;   // B: k offset 0/8 (lanes 16-31 mirror)

    // stage a 128x64 bf16 tile (rows of 128B, SW128) via cp.async
    auto stage4 = [&](char* dst, const __nv_bfloat16* g, int row0, int k0) {
#pragma unroll
        for (int c = tid; c < 1024; c += 256) {
            int row = c >> 3, cc = c & 7;
            cp_async16(dst + SWZ128(row * 128 + cc * 16),
                       g + (size_t)(row0 + row) * 512 + k0 + cc * 8);
        }
    };
    auto stage_all = [&](int s, int k0) {
        char* p = smc + 1024 + (s & 1) * 65536;
        stage4(p,         Ahi, m0, k0);
        stage4(p + 16384, Alo, m0, k0);
        stage4(p + 32768, Bhi, n0, k0);
        stage4(p + 49152, Blo, n0, k0);
        cp_commit();
    };

    float acc[4][4][4];
#pragma unroll
    for (int i = 0; i < 4; i++)
#pragma unroll
        for (int j = 0; j < 4; j++)
#pragma unroll
            for (int e = 0; e < 4; e++) acc[i][j][e] = 0.f;

    stage_all(0, 0);

    for (int it = 0; it < 8; it++) {
        cp_wait<0>();
        __syncthreads();
        if (it < 7) stage_all(it + 1, (it + 1) * 64);

        const unsigned off  = sbase + 1024 + (unsigned)(it & 1) * 65536;
        const unsigned aHi = off, aLo = off + 16384, bHi = off + 32768, bLo = off + 49152;

#pragma unroll
        for (int ks = 0; ks < 4; ks++) {
            // B fragments for 4 n-tiles (hi & lo)
            unsigned bh[4][2], bl[4][2];
#pragma unroll
            for (int j = 0; j < 4; j++) {
                unsigned boff = SWZ128((unsigned)((nw * 32 + j * 8 + bRow) * 128
                                                  + (ks * 16 + bKof) * 2));
                ldsm_x2(bh[j][0], bh[j][1], bHi + boff);
                ldsm_x2(bl[j][0], bl[j][1], bLo + boff);
            }
#pragma unroll
            for (int im = 0; im < 4; im++) {
                unsigned aoff = SWZ128((unsigned)((mw * 64 + im * 16 + aRow) * 128
                                                  + (ks * 16 + aKof) * 2));
                unsigned ah[4], al[4];
                ldsm_x4(ah[0], ah[1], ah[2], ah[3], aHi + aoff);
                ldsm_x4(al[0], al[1], al[2], al[3], aLo + aoff);
#pragma unroll
                for (int j = 0; j < 4; j++) {
                    mma_bf16(acc[im][j], ah, bh[j]);
                    mma_bf16(acc[im][j], ah, bl[j]);
                    mma_bf16(acc[im][j], al, bh[j]);
                }
            }
        }
        __syncthreads();
    }

    // epilogue: register accumulators -> C with bias (float2 stores)
#pragma unroll
    for (int im = 0; im < 4; im++) {
#pragma unroll
        for (int j = 0; j < 4; j++) {
            const int colL = nw * 32 + j * 8 + tig * 2;     // local col within 128
            const int col  = n0 + colL;
            const int row0 = m0 + mw * 64 + im * 16 + grp;
            float2 v0, v1;
            v0.x = acc[im][j][0] + bs[colL];
            v0.y = acc[im][j][1] + bs[colL + 1];
            v1.x = acc[im][j][2] + bs[colL];
            v1.y = acc[im][j][3] + bs[colL + 1];
            *(float2*)&C[(size_t)row0 * G_ + col]       = v0;
            *(float2*)&C[(size_t)(row0 + 8) * G_ + col] = v1;
        }
    }
}

// ---------------- persistent LSTM layer (round-7 verbatim; hseq row-major write) ---------
__global__ void __launch_bounds__(256, 1) lstm_persistent(const float* __restrict__ xw,
                                                          const float* __restrict__ Wh,
                                                          float* __restrict__ hseq)
{
    extern __shared__ float sm[];
    float* h_s = sm;                 // 512*64 = 32768
    float* w_s = sm + 32768;         // 512*16 =  8192
    float* red = w_s + 8192;         // 3*64*16 = 3072
    float* z_s = red + 3072;         // 64*16  =  1024
    float* c_s = z_s + 1024;         // 64*4   =   256

    const int tid = threadIdx.x;
    const int hc0 = blockIdx.x * 4;

    for (int i = tid; i < 512 * 4; i += 256) {
        int k = i >> 2, g = i & 3;
        *(float4*)(w_s + k * 16 + g * 4) =
            *(const float4*)(Wh + (size_t)k * G_ + g * H_ + hc0);
    }
    c_s[tid] = 0.f;
    {
        int c = tid >> 6, b = tid & 63;
        g_hbufT[(hc0 + c) * B_ + b] = 0.f;
    }
    __threadfence();
    grid_barrier();

    const int q  = tid >> 6;
    const int r  = tid & 63;
    const int rg = r & 15;
    const int cg = r >> 4;

    for (int t = 0; t < T_; t++) {
        const float* hsrc = g_hbufT + (t & 1) * (H_ * B_);
        float*       hdst = g_hbufT + ((t & 1) ^ 1) * (H_ * B_);
        const float4* hsrc4 = (const float4*)hsrc;

        float4 xv0, xv1, xv2, xv3;
        if (q == 0) {
            const float* xp = xw + (size_t)(4 * rg * T_ + t) * G_ + cg * H_ + hc0;
            xv0 = *(const float4*)(xp);
            xv1 = *(const float4*)(xp + (size_t)T_ * G_);
            xv2 = *(const float4*)(xp + (size_t)2 * T_ * G_);
            xv3 = *(const float4*)(xp + (size_t)3 * T_ * G_);
        }

#pragma unroll
        for (int j = 0; j < 8; j++) {
            int idx = tid + j * 256;
            cp_async16(h_s + idx * 4, hsrc4 + idx);
        }
        cp_commit();

        ull accP[4][2];
#pragma unroll
        for (int i = 0; i < 4; i++) { accP[i][0] = 0ull; accP[i][1] = 0ull; }

#pragma unroll
        for (int c = 0; c < 4; c++) {
            if (c < 3) {
#pragma unroll
                for (int j = 0; j < 8; j++) {
                    int idx = (c + 1) * 2048 + tid + j * 256;
                    cp_async16(h_s + idx * 4, hsrc4 + idx);
                }
                cp_commit();
                cp_wait<1>();
            } else {
                cp_wait<0>();
            }
            __syncthreads();

            const float* hp = h_s + (c * 128 + q * 32) * 64 + 4 * rg;
            const float* wp = w_s + (c * 128 + q * 32) * 16 + 4 * cg;
#pragma unroll 8
            for (int kk = 0; kk < 32; kk++) {
                float4 hv = *(const float4*)(hp + kk * 64);
                ulonglong2 wv = *(const ulonglong2*)(wp + kk * 16);
                ull h0 = pack2(hv.x, hv.x);
                ull h1 = pack2(hv.y, hv.y);
                ull h2 = pack2(hv.z, hv.z);
                ull h3 = pack2(hv.w, hv.w);
                ffma2(accP[0][0], h0, wv.x); ffma2(accP[0][1], h0, wv.y);
                ffma2(accP[1][0], h1, wv.x); ffma2(accP[1][1], h1, wv.y);
                ffma2(accP[2][0], h2, wv.x); ffma2(accP[2][1], h2, wv.y);
                ffma2(accP[3][0], h3, wv.x); ffma2(accP[3][1], h3, wv.y);
            }
        }

        float acc[4][4];
#pragma unroll
        for (int i = 0; i < 4; i++) {
            unpack2(accP[i][0], acc[i][0], acc[i][1]);
            unpack2(accP[i][1], acc[i][2], acc[i][3]);
        }

        if (q) {
            float* rp = red + ((q - 1) * 64 + r) * 16;
#pragma unroll
            for (int i = 0; i < 4; i++)
#pragma unroll
                for (int j = 0; j < 4; j++) rp[i * 4 + j] = acc[i][j];
        }
        __syncthreads();

        if (q == 0) {
#pragma unroll
            for (int qq = 0; qq < 3; qq++) {
                const float* rp = red + (qq * 64 + r) * 16;
#pragma unroll
                for (int i = 0; i < 4; i++)
#pragma unroll
                    for (int j = 0; j < 4; j++) acc[i][j] += rp[i * 4 + j];
            }
            float4 xv[4] = {xv0, xv1, xv2, xv3};
#pragma unroll
            for (int i = 0; i < 4; i++) {
                const float* xf = (const float*)&xv[i];
#pragma unroll
                for (int j = 0; j < 4; j++)
                    z_s[(4 * rg + i) * 16 + 4 * cg + j] = acc[i][j] + xf[j];
            }
        }
        __syncthreads();

        {
            const int b = tid >> 2, c = tid & 3;
            float zi = z_s[b * 16 + 0  + c];
            float zf = z_s[b * 16 + 4  + c];
            float zg = z_s[b * 16 + 8  + c];
            float zo = z_s[b * 16 + 12 + c];
            float ig = 1.f / (1.f + expf(-zi));
            float fg = 1.f / (1.f + expf(-zf));
            float gg = tanhf(zg);
            float og = 1.f / (1.f + expf(-zo));
            float cc = fmaf(fg, c_s[tid], ig * gg);
            c_s[tid] = cc;
            float hh = og * tanhf(cc);
            hdst[(hc0 + c) * B_ + b] = hh;
            if (hseq)
                hseq[(size_t)(b * T_ + t) * H_ + hc0 + c] = hh;   // row-major [M][H]
        }
        grid_barrier();
    }
}

// ---------------- head: out[b] = relu(relu(h@Wd1 + bd1) @ Wd2 + bd2) ----------------
__global__ void __launch_bounds__(256) head_kernel(const float* __restrict__ Wd1,
                                                   const float* __restrict__ bd1,
                                                   const float* __restrict__ Wd2,
                                                   const float* __restrict__ bd2,
                                                   float* __restrict__ out)
{
    const int b = blockIdx.x;
    const int j = threadIdx.x;
    const float* hT = g_hbufT;
    float acc = 0.f;
#pragma unroll 8
    for (int k = 0; k < H_; k++)
        acc = fmaf(hT[k * B_ + b], Wd1[k * (H_ / 2) + j], acc);
    float t1 = fmaxf(acc + bd1[j], 0.f);
    float p  = t1 * Wd2[j];
    __shared__ float s[256];
    s[j] = p;
    __syncthreads();
    for (int off = 128; off; off >>= 1) {
        if (j < off) s[j] += s[j + off];
        __syncthreads();
    }
    if (j == 0) out[b] = fmaxf(s[0] + bd2[0], 0.f);
}

// ---------------- launch ----------------
extern "C" void kernel_launch(void* const* d_in, const int* in_sizes, int n_in,
                              void* d_out, int out_size)
{
    (void)in_sizes; (void)n_in; (void)out_size;
    const float* x   = (const float*)d_in[0];
    const float* Wi1 = (const float*)d_in[2];
    const float* Wh1 = (const float*)d_in[3];
    const float* b1  = (const float*)d_in[4];
    const float* Wi2 = (const float*)d_in[5];
    const float* Wh2 = (const float*)d_in[6];
    const float* b2  = (const float*)d_in[7];
    const float* Wd1 = (const float*)d_in[8];
    const float* bd1 = (const float*)d_in[9];
    const float* Wd2 = (const float*)d_in[10];
    const float* bd2 = (const float*)d_in[11];
    float* out = (float*)d_out;

    float *xT, *xwb, *hseq;
    __nv_bfloat16 *Ahi, *Alo, *Bhi, *Blo;
    cudaGetSymbolAddress((void**)&xT,   g_xT);
    cudaGetSymbolAddress((void**)&xwb,  g_xw);
    cudaGetSymbolAddress((void**)&hseq, g_hseq);
    cudaGetSymbolAddress((void**)&Ahi,  g_Ahi);
    cudaGetSymbolAddress((void**)&Alo,  g_Alo);
    cudaGetSymbolAddress((void**)&Bhi,  g_Bhi);
    cudaGetSymbolAddress((void**)&Blo,  g_Blo);

    const size_t smem = (32768 + 8192 + 3072 + 1024 + 256) * sizeof(float); // 181248 B
    cudaFuncSetAttribute(lstm_persistent,
                         cudaFuncAttributeMaxDynamicSharedMemorySize, (int)smem);
    const size_t smem_tc = 1024 + 2 * 65536;   // 132096 B
    cudaFuncSetAttribute(gemm_tc,
                         cudaFuncAttributeMaxDynamicSharedMemorySize, (int)smem_tc);

    transpose_x<<<dim3(1024, 2), dim3(32, 8)>>>(x, xT);
    cvt_wi2t<<<(G_ * H_) / 256, 256>>>(Wi2, Bhi, Blo);
    gemm_atb<<<dim3(G_ / 64, M_ / 64), 256>>>(xT, Wi1, b1, xwb, M_, G_, F_);
    lstm_persistent<<<NCTA_, 256, smem>>>(xwb, Wh1, hseq);
    cvt_split<<<(int)(((size_t)M_ * H_) / 256), 256>>>(hseq, Ahi, Alo);
    gemm_tc<<<dim3(G_ / 128, M_ / 128), 256, smem_tc>>>(Ahi, Alo, Bhi, Blo, b2, xwb);
    lstm_persistent<<<NCTA_, 256, smem>>>(xwb, Wh2, nullptr);
    head_kernel<<<B_, 256>>>(Wd1, bd1, Wd2, bd2, out);
}

// round 10
// speedup vs baseline: 2.5860x; 1.0186x over previous
#include <cuda_runtime.h>
#include <cuda_bf16.h>
#include <math.h>

#define B_    64
#define T_    512
#define F_    64
#define H_    512
#define G_    2048          // 4*H
#define M_    (B_*T_)       // 32768
#define NCTA_ 128

typedef unsigned long long ull;

// ---------------- packed f32x2 helpers (validated round 4) ----------------
__device__ __forceinline__ void ffma2(ull& acc, ull a, ull b) {
    asm("fma.rn.f32x2 %0, %1, %2, %0;" : "+l"(acc) : "l"(a), "l"(b));
}
__device__ __forceinline__ void fadd2(ull& acc, ull b) {
    asm("add.rn.f32x2 %0, %0, %1;" : "+l"(acc) : "l"(b));
}
__device__ __forceinline__ ull pack2(float lo, float hi) {
    ull r; asm("mov.b64 %0, {%1, %2};" : "=l"(r) : "f"(lo), "f"(hi)); return r;
}
__device__ __forceinline__ void unpack2(ull v, float& lo, float& hi) {
    asm("mov.b64 {%0, %1}, %2;" : "=f"(lo), "=f"(hi) : "l"(v));
}

// ---------------- cp.async helpers ----------------
__device__ __forceinline__ void cp_async16(void* smem_dst, const void* gsrc) {
    unsigned s = (unsigned)__cvta_generic_to_shared(smem_dst);
    asm volatile("cp.async.cg.shared.global [%0], [%1], 16;" :: "r"(s), "l"(gsrc));
}
__device__ __forceinline__ void cp_commit() {
    asm volatile("cp.async.commit_group;");
}
template <int N>
__device__ __forceinline__ void cp_wait() {
    asm volatile("cp.async.wait_group %0;" :: "n"(N));
}

// ---------------- HMMA (mma.sync) helpers — baseline PTX, sm_80+ ----------------
#define SWZ128(x) ((x) ^ (((x) >> 3) & 0x70))

__device__ __forceinline__ void ldsm_x4(unsigned& r0, unsigned& r1, unsigned& r2, unsigned& r3,
                                        unsigned addr) {
    asm volatile("ldmatrix.sync.aligned.m8n8.x4.shared.b16 {%0,%1,%2,%3}, [%4];"
                 : "=r"(r0), "=r"(r1), "=r"(r2), "=r"(r3) : "r"(addr));
}
__device__ __forceinline__ void ldsm_x2(unsigned& r0, unsigned& r1, unsigned addr) {
    asm volatile("ldmatrix.sync.aligned.m8n8.x2.shared.b16 {%0,%1}, [%2];"
                 : "=r"(r0), "=r"(r1) : "r"(addr));
}
__device__ __forceinline__ void mma_bf16(float* c, const unsigned* a, const unsigned* b) {
    asm volatile("mma.sync.aligned.m16n8k16.row.col.f32.bf16.bf16.f32 "
                 "{%0,%1,%2,%3}, {%4,%5,%6,%7}, {%8,%9}, {%0,%1,%2,%3};"
                 : "+f"(c[0]), "+f"(c[1]), "+f"(c[2]), "+f"(c[3])
                 : "r"(a[0]), "r"(a[1]), "r"(a[2]), "r"(a[3]), "r"(b[0]), "r"(b[1]));
}

// ---------------- scratch (static device allocations only) ----------------
__device__ float g_xT[(size_t)F_ * M_];       //   8 MB : x transposed [F][M]
__device__ float g_xw[(size_t)M_ * G_];       // 256 MB : xW (+bias) [M][G]
__device__ float g_hseq[(size_t)M_ * H_];     //  64 MB : layer-1 output [M][H] (row-major)
__device__ float g_hbufT[2 * H_ * B_];        // double-buffered h state, transposed [H][B]
__device__ __nv_bfloat16 g_Ahi[(size_t)M_ * H_];   // 32 MB split-bf16 of hseq
__device__ __nv_bfloat16 g_Alo[(size_t)M_ * H_];
__device__ __nv_bfloat16 g_Bhi[(size_t)G_ * H_];   // 2 MB : Wi2^T split-bf16 [N][K]
__device__ __nv_bfloat16 g_Blo[(size_t)G_ * H_];
__device__ unsigned g_cnt8[8 * 32];
__device__ unsigned g_gen8[8 * 32];
__device__ unsigned g_done8;

// acquire load (plain load — same-address polls broadcast, no L2 serialization)
__device__ __forceinline__ unsigned ld_acq(const unsigned* p) {
    unsigned v;
    asm volatile("ld.acquire.gpu.global.u32 %0, [%1];" : "=r"(v) : "l"(p));
    return v;
}

// ---------------- grid-wide barrier: sharded arrivals + load-poll release ----------------
__device__ __forceinline__ void grid_barrier()
{
    __syncthreads();
    if (threadIdx.x == 0) {
        const unsigned lane = blockIdx.x & 7u;          // 16 CTAs per lane
        unsigned* cntp = &g_cnt8[lane * 32];
        unsigned* genp = &g_gen8[lane * 32];
        __threadfence();
        unsigned gen = ld_acq(genp);
        unsigned arrived = atomicAdd(cntp, 1u);
        if (arrived == 15u) {                            // lane closer
            atomicExch(cntp, 0u);
            unsigned d = atomicAdd(&g_done8, 1u);
            if (d == 7u) {                               // final closer: release all
                atomicExch(&g_done8, 0u);
                __threadfence();
#pragma unroll
                for (int l = 0; l < 8; l++)
                    atomicAdd(&g_gen8[l * 32], 1u);
            } else {
                while (ld_acq(genp) == gen) { __nanosleep(32); }
            }
        } else {
            while (ld_acq(genp) == gen) { __nanosleep(32); }
        }
        __threadfence();
    }
    __syncthreads();
}

// ---------------- x transpose: x[M][F] -> xT[F][M] ----------------
__global__ void __launch_bounds__(256) transpose_x(const float* __restrict__ x,
                                                   float* __restrict__ xT)
{
    __shared__ float tile[32][33];
    const int m0 = blockIdx.x * 32;
    const int f0 = blockIdx.y * 32;
    const int tx = threadIdx.x, ty = threadIdx.y;
#pragma unroll
    for (int i = 0; i < 32; i += 8)
        tile[ty + i][tx] = x[(size_t)(m0 + ty + i) * F_ + f0 + tx];
    __syncthreads();
#pragma unroll
    for (int i = 0; i < 32; i += 8)
        xT[(size_t)(f0 + ty + i) * M_ + m0 + tx] = tile[tx][ty + i];
}

// ---------------- split-bf16 conversions ----------------
__global__ void __launch_bounds__(256) cvt_split(const float* __restrict__ src,
                                                 __nv_bfloat16* __restrict__ hi,
                                                 __nv_bfloat16* __restrict__ lo)
{
    size_t i = (size_t)blockIdx.x * 256 + threadIdx.x;
    float x = src[i];
    __nv_bfloat16 h = __float2bfloat16(x);
    hi[i] = h;
    lo[i] = __float2bfloat16(x - __bfloat162float(h));
}
// Bhi[n][k] = split(Wi2[k][n])
__global__ void __launch_bounds__(256) cvt_wi2t(const float* __restrict__ Wi2,
                                                __nv_bfloat16* __restrict__ hi,
                                                __nv_bfloat16* __restrict__ lo)
{
    int i = blockIdx.x * 256 + threadIdx.x;          // i over G_*H_
    int n = i >> 9, k = i & 511;
    float x = Wi2[(size_t)k * G_ + n];
    __nv_bfloat16 h = __float2bfloat16(x);
    hi[i] = h;
    lo[i] = __float2bfloat16(x - __bfloat162float(h));
}

// ---------------- GEMM (FFMA2, proven) — used for GEMM1 only ----------------
__global__ void __launch_bounds__(256) gemm_atb(const float* __restrict__ AT,
                                                const float* __restrict__ Bm,
                                                const float* __restrict__ bias,
                                                float* __restrict__ C,
                                                int M, int N, int K)
{
    __shared__ float As[2][16 * 64];
    __shared__ float Bs[2][16 * 64];
    const int tid = threadIdx.x;
    const int tx = tid & 15, ty = tid >> 4;
    const int m0 = blockIdx.y * 64, n0 = blockIdx.x * 64;
    const int lr = tid >> 4, lc4 = (tid & 15) * 4;

    const float* ap = AT + (size_t)lr * M + m0 + lc4;
    const float* bp = Bm + (size_t)lr * N + n0 + lc4;
    float4 aReg = *(const float4*)ap;
    float4 bReg = *(const float4*)bp;

    ull accP[4][2];
#pragma unroll
    for (int i = 0; i < 4; i++) { accP[i][0] = 0ull; accP[i][1] = 0ull; }

    const int NT = K >> 4;
    for (int kt = 0; kt < NT; kt++) {
        const int cur = kt & 1;
        *(float4*)&As[cur][lr * 64 + lc4] = aReg;
        *(float4*)&Bs[cur][lr * 64 + lc4] = bReg;
        __syncthreads();
        if (kt + 1 < NT) {
            aReg = *(const float4*)(ap + (size_t)(kt + 1) * 16 * M);
            bReg = *(const float4*)(bp + (size_t)(kt + 1) * 16 * N);
        }
#pragma unroll
        for (int kk = 0; kk < 16; kk++) {
            float4 a = *(const float4*)&As[cur][kk * 64 + ty * 4];
            ulonglong2 bv = *(const ulonglong2*)&Bs[cur][kk * 64 + tx * 4];
            ull a0 = pack2(a.x, a.x);
            ull a1 = pack2(a.y, a.y);
            ull a2 = pack2(a.z, a.z);
            ull a3 = pack2(a.w, a.w);
            ffma2(accP[0][0], a0, bv.x); ffma2(accP[0][1], a0, bv.y);
            ffma2(accP[1][0], a1, bv.x); ffma2(accP[1][1], a1, bv.y);
            ffma2(accP[2][0], a2, bv.x); ffma2(accP[2][1], a2, bv.y);
            ffma2(accP[3][0], a3, bv.x); ffma2(accP[3][1], a3, bv.y);
        }
    }
    float acc[4][4];
#pragma unroll
    for (int i = 0; i < 4; i++) {
        unpack2(accP[i][0], acc[i][0], acc[i][1]);
        unpack2(accP[i][1], acc[i][2], acc[i][3]);
    }
    float4 bv = *(const float4*)(bias + n0 + tx * 4);
#pragma unroll
    for (int i = 0; i < 4; i++) {
        float4 o;
        o.x = acc[i][0] + bv.x;
        o.y = acc[i][1] + bv.y;
        o.z = acc[i][2] + bv.z;
        o.w = acc[i][3] + bv.w;
        *(float4*)&C[(size_t)(m0 + ty * 4 + i) * N + n0 + tx * 4] = o;
    }
}

// ---------------- HMMA GEMM2 (round-9 verbatim, proven) ----------------
__global__ void __launch_bounds__(256, 1) gemm_tc(const __nv_bfloat16* __restrict__ Ahi,
                                                  const __nv_bfloat16* __restrict__ Alo,
                                                  const __nv_bfloat16* __restrict__ Bhi,
                                                  const __nv_bfloat16* __restrict__ Blo,
                                                  const float* __restrict__ bias,
                                                  float* __restrict__ C)
{
    extern __shared__ char smc[];
    float* bs = (float*)(smc + 128);
    const int tid = threadIdx.x;
    const int wid = tid >> 5, lane = tid & 31;
    const int m0 = blockIdx.y * 128, n0 = blockIdx.x * 128;

    if (tid < 128) bs[tid] = bias[n0 + tid];

    const int mw = wid & 1;
    const int nw = wid >> 1;
    const int grp = lane >> 2, tig = lane & 3;

    const int aRow = lane & 15;
    const int aKof = (lane >> 4) << 3;
    const int bRow = lane & 7;
    const int bKof = ((lane >> 3) & 1) << 3;
    const unsigned sbase = (unsigned)__cvta_generic_to_shared(smc);

    auto stage4 = [&](char* dst, const __nv_bfloat16* g, int row0, int k0) {
#pragma unroll
        for (int c = tid; c < 1024; c += 256) {
            int row = c >> 3, cc = c & 7;
            cp_async16(dst + SWZ128(row * 128 + cc * 16),
                       g + (size_t)(row0 + row) * 512 + k0 + cc * 8);
        }
    };
    auto stage_all = [&](int s, int k0) {
        char* p = smc + 1024 + (s & 1) * 65536;
        stage4(p,         Ahi, m0, k0);
        stage4(p + 16384, Alo, m0, k0);
        stage4(p + 32768, Bhi, n0, k0);
        stage4(p + 49152, Blo, n0, k0);
        cp_commit();
    };

    float acc[4][4][4];
#pragma unroll
    for (int i = 0; i < 4; i++)
#pragma unroll
        for (int j = 0; j < 4; j++)
#pragma unroll
            for (int e = 0; e < 4; e++) acc[i][j][e] = 0.f;

    stage_all(0, 0);

    for (int it = 0; it < 8; it++) {
        cp_wait<0>();
        __syncthreads();
        if (it < 7) stage_all(it + 1, (it + 1) * 64);

        const unsigned off  = sbase + 1024 + (unsigned)(it & 1) * 65536;
        const unsigned aHi = off, aLo = off + 16384, bHi = off + 32768, bLo = off + 49152;

#pragma unroll
        for (int ks = 0; ks < 4; ks++) {
            unsigned bh[4][2], bl[4][2];
#pragma unroll
            for (int j = 0; j < 4; j++) {
                unsigned boff = SWZ128((unsigned)((nw * 32 + j * 8 + bRow) * 128
                                                  + (ks * 16 + bKof) * 2));
                ldsm_x2(bh[j][0], bh[j][1], bHi + boff);
                ldsm_x2(bl[j][0], bl[j][1], bLo + boff);
            }
#pragma unroll
            for (int im = 0; im < 4; im++) {
                unsigned aoff = SWZ128((unsigned)((mw * 64 + im * 16 + aRow) * 128
                                                  + (ks * 16 + aKof) * 2));
                unsigned ah[4], al[4];
                ldsm_x4(ah[0], ah[1], ah[2], ah[3], aHi + aoff);
                ldsm_x4(al[0], al[1], al[2], al[3], aLo + aoff);
#pragma unroll
                for (int j = 0; j < 4; j++) {
                    mma_bf16(acc[im][j], ah, bh[j]);
                    mma_bf16(acc[im][j], ah, bl[j]);
                    mma_bf16(acc[im][j], al, bh[j]);
                }
            }
        }
        __syncthreads();
    }

#pragma unroll
    for (int im = 0; im < 4; im++) {
#pragma unroll
        for (int j = 0; j < 4; j++) {
            const int colL = nw * 32 + j * 8 + tig * 2;
            const int col  = n0 + colL;
            const int row0 = m0 + mw * 64 + im * 16 + grp;
            float2 v0, v1;
            v0.x = acc[im][j][0] + bs[colL];
            v0.y = acc[im][j][1] + bs[colL + 1];
            v1.x = acc[im][j][2] + bs[colL];
            v1.y = acc[im][j][3] + bs[colL + 1];
            *(float2*)&C[(size_t)row0 * G_ + col]       = v0;
            *(float2*)&C[(size_t)(row0 + 8) * G_ + col] = v1;
        }
    }
}

// ---------------- persistent LSTM layer: 512 threads, 8-way interleaved k-split --------
// 128 CTAs, each owns 4 hidden cols (16 gate cols). z = xw[:,t,:] + h@Wh.
// 16 warps/CTA for latency hiding. Group q computes k-stripes [c*128+q*16, +16) per chunk.
__global__ void __launch_bounds__(512, 1) lstm_persistent(const float* __restrict__ xw,
                                                          const float* __restrict__ Wh,
                                                          float* __restrict__ hseq)
{
    extern __shared__ float sm[];
    float* h_s = sm;                 // 512*64 = 32768
    float* w_s = sm + 32768;         // 512*16 =  8192
    float* red = w_s + 8192;         // 7*64*16 = 7168
    float* z_s = red + 7168;         // 64*16  =  1024
    float* c_s = z_s + 1024;         // 64*4   =   256  (total 49408 floats = 197632 B)

    const int tid = threadIdx.x;
    const int hc0 = blockIdx.x * 4;

    // load Wh slice: w_s[k][g*4+c] = Wh[k][g*512 + hc0 + c]
    for (int i = tid; i < 512 * 4; i += 512) {
        int k = i >> 2, g = i & 3;
        *(float4*)(w_s + k * 16 + g * 4) =
            *(const float4*)(Wh + (size_t)k * G_ + g * H_ + hc0);
    }
    if (tid < 256) {
        c_s[tid] = 0.f;
        int c = tid >> 6, b = tid & 63;
        g_hbufT[(hc0 + c) * B_ + b] = 0.f;   // zero h buf0 (this CTA's slice)
    }
    __threadfence();
    grid_barrier();

    const int q  = tid >> 6;   // 8-way k-split group
    const int r  = tid & 63;
    const int rg = r & 15;     // batch rows 4*rg .. 4*rg+3
    const int cg = r >> 4;     // gate index 0..3 (tile cols 4*cg..4*cg+3)

    for (int t = 0; t < T_; t++) {
        const float* hsrc = g_hbufT + (t & 1) * (H_ * B_);
        float*       hdst = g_hbufT + ((t & 1) ^ 1) * (H_ * B_);
        const float4* hsrc4 = (const float4*)hsrc;

        // prefetch xw first (DRAM latency; q==0 threads only)
        float4 xv0, xv1, xv2, xv3;
        if (q == 0) {
            const float* xp = xw + (size_t)(4 * rg * T_ + t) * G_ + cg * H_ + hc0;
            xv0 = *(const float4*)(xp);
            xv1 = *(const float4*)(xp + (size_t)T_ * G_);
            xv2 = *(const float4*)(xp + (size_t)2 * T_ * G_);
            xv3 = *(const float4*)(xp + (size_t)3 * T_ * G_);
        }

        // issue chunk 0 (k rows [0,128) = float4 idx [0,2048))
#pragma unroll
        for (int j = 0; j < 4; j++) {
            int idx = tid + j * 512;
            cp_async16(h_s + idx * 4, hsrc4 + idx);
        }
        cp_commit();

        ull accP[4][2];
#pragma unroll
        for (int i = 0; i < 4; i++) { accP[i][0] = 0ull; accP[i][1] = 0ull; }

#pragma unroll
        for (int c = 0; c < 4; c++) {
            if (c < 3) {
#pragma unroll
                for (int j = 0; j < 4; j++) {
                    int idx = (c + 1) * 2048 + tid + j * 512;
                    cp_async16(h_s + idx * 4, hsrc4 + idx);
                }
                cp_commit();
                cp_wait<1>();
            } else {
                cp_wait<0>();
            }
            __syncthreads();

            // compute this group's stripe of chunk c: k in [c*128 + q*16, +16)
            const float* hp = h_s + (c * 128 + q * 16) * 64 + 4 * rg;
            const float* wp = w_s + (c * 128 + q * 16) * 16 + 4 * cg;
#pragma unroll
            for (int kk = 0; kk < 16; kk++) {
                float4 hv = *(const float4*)(hp + kk * 64);
                ulonglong2 wv = *(const ulonglong2*)(wp + kk * 16);
                ull h0 = pack2(hv.x, hv.x);
                ull h1 = pack2(hv.y, hv.y);
                ull h2 = pack2(hv.z, hv.z);
                ull h3 = pack2(hv.w, hv.w);
                ffma2(accP[0][0], h0, wv.x); ffma2(accP[0][1], h0, wv.y);
                ffma2(accP[1][0], h1, wv.x); ffma2(accP[1][1], h1, wv.y);
                ffma2(accP[2][0], h2, wv.x); ffma2(accP[2][1], h2, wv.y);
                ffma2(accP[3][0], h3, wv.x); ffma2(accP[3][1], h3, wv.y);
            }
        }

        // ---- 8-way k-split reduction ----
        if (q) {
            float* rp = red + ((q - 1) * 64 + r) * 16;
#pragma unroll
            for (int i = 0; i < 4; i++) {
                *(ull*)(rp + i * 4)     = accP[i][0];
                *(ull*)(rp + i * 4 + 2) = accP[i][1];
            }
        }
        __syncthreads();

        if (q == 0) {
#pragma unroll
            for (int qq = 0; qq < 7; qq++) {
                const float* rp = red + (qq * 64 + r) * 16;
#pragma unroll
                for (int i = 0; i < 4; i++) {
                    fadd2(accP[i][0], *(const ull*)(rp + i * 4));
                    fadd2(accP[i][1], *(const ull*)(rp + i * 4 + 2));
                }
            }
            float acc[4][4];
#pragma unroll
            for (int i = 0; i < 4; i++) {
                unpack2(accP[i][0], acc[i][0], acc[i][1]);
                unpack2(accP[i][1], acc[i][2], acc[i][3]);
            }
            float4 xv[4] = {xv0, xv1, xv2, xv3};
#pragma unroll
            for (int i = 0; i < 4; i++) {
                const float* xf = (const float*)&xv[i];
#pragma unroll
                for (int j = 0; j < 4; j++)
                    z_s[(4 * rg + i) * 16 + 4 * cg + j] = acc[i][j] + xf[j];
            }
        }
        __syncthreads();

        // state update: threads 0..255 -> (b = tid>>2, c = tid&3)
        if (tid < 256) {
            const int b = tid >> 2, c = tid & 3;
            float zi = z_s[b * 16 + 0  + c];
            float zf = z_s[b * 16 + 4  + c];
            float zg = z_s[b * 16 + 8  + c];
            float zo = z_s[b * 16 + 12 + c];
            float ig = 1.f / (1.f + expf(-zi));
            float fg = 1.f / (1.f + expf(-zf));
            float gg = tanhf(zg);
            float og = 1.f / (1.f + expf(-zo));
            float cc = fmaf(fg, c_s[tid], ig * gg);
            c_s[tid] = cc;
            float hh = og * tanhf(cc);
            hdst[(hc0 + c) * B_ + b] = hh;
            if (hseq)
                hseq[(size_t)(b * T_ + t) * H_ + hc0 + c] = hh;   // row-major [M][H]
        }
        grid_barrier();
    }
}

// ---------------- head: out[b] = relu(relu(h@Wd1 + bd1) @ Wd2 + bd2) ----------------
__global__ void __launch_bounds__(256) head_kernel(const float* __restrict__ Wd1,
                                                   const float* __restrict__ bd1,
                                                   const float* __restrict__ Wd2,
                                                   const float* __restrict__ bd2,
                                                   float* __restrict__ out)
{
    const int b = blockIdx.x;
    const int j = threadIdx.x;
    const float* hT = g_hbufT;
    float acc = 0.f;
#pragma unroll 8
    for (int k = 0; k < H_; k++)
        acc = fmaf(hT[k * B_ + b], Wd1[k * (H_ / 2) + j], acc);
    float t1 = fmaxf(acc + bd1[j], 0.f);
    float p  = t1 * Wd2[j];
    __shared__ float s[256];
    s[j] = p;
    __syncthreads();
    for (int off = 128; off; off >>= 1) {
        if (j < off) s[j] += s[j + off];
        __syncthreads();
    }
    if (j == 0) out[b] = fmaxf(s[0] + bd2[0], 0.f);
}

// ---------------- launch ----------------
extern "C" void kernel_launch(void* const* d_in, const int* in_sizes, int n_in,
                              void* d_out, int out_size)
{
    (void)in_sizes; (void)n_in; (void)out_size;
    const float* x   = (const float*)d_in[0];
    const float* Wi1 = (const float*)d_in[2];
    const float* Wh1 = (const float*)d_in[3];
    const float* b1  = (const float*)d_in[4];
    const float* Wi2 = (const float*)d_in[5];
    const float* Wh2 = (const float*)d_in[6];
    const float* b2  = (const float*)d_in[7];
    const float* Wd1 = (const float*)d_in[8];
    const float* bd1 = (const float*)d_in[9];
    const float* Wd2 = (const float*)d_in[10];
    const float* bd2 = (const float*)d_in[11];
    float* out = (float*)d_out;

    float *xT, *xwb, *hseq;
    __nv_bfloat16 *Ahi, *Alo, *Bhi, *Blo;
    cudaGetSymbolAddress((void**)&xT,   g_xT);
    cudaGetSymbolAddress((void**)&xwb,  g_xw);
    cudaGetSymbolAddress((void**)&hseq, g_hseq);
    cudaGetSymbolAddress((void**)&Ahi,  g_Ahi);
    cudaGetSymbolAddress((void**)&Alo,  g_Alo);
    cudaGetSymbolAddress((void**)&Bhi,  g_Bhi);
    cudaGetSymbolAddress((void**)&Blo,  g_Blo);

    const size_t smem = (32768 + 8192 + 7168 + 1024 + 256) * sizeof(float); // 197632 B
    cudaFuncSetAttribute(lstm_persistent,
                         cudaFuncAttributeMaxDynamicSharedMemorySize, (int)smem);
    const size_t smem_tc = 1024 + 2 * 65536;   // 132096 B
    cudaFuncSetAttribute(gemm_tc,
                         cudaFuncAttributeMaxDynamicSharedMemorySize, (int)smem_tc);

    transpose_x<<<dim3(1024, 2), dim3(32, 8)>>>(x, xT);
    cvt_wi2t<<<(G_ * H_) / 256, 256>>>(Wi2, Bhi, Blo);
    gemm_atb<<<dim3(G_ / 64, M_ / 64), 256>>>(xT, Wi1, b1, xwb, M_, G_, F_);
    lstm_persistent<<<NCTA_, 512, smem>>>(xwb, Wh1, hseq);
    cvt_split<<<(int)(((size_t)M_ * H_) / 256), 256>>>(hseq, Ahi, Alo);
    gemm_tc<<<dim3(G_ / 128, M_ / 128), 256, smem_tc>>>(Ahi, Alo, Bhi, Blo, b2, xwb);
    lstm_persistent<<<NCTA_, 512, smem>>>(xwb, Wh2, nullptr);
    head_kernel<<<B_, 256>>>(Wd1, bd1, Wd2, bd2, out);
}

// round 11
// speedup vs baseline: 3.1490x; 1.2177x over previous
#include <cuda_runtime.h>
#include <math.h>

#define B_    64
#define T_    512
#define F_    64
#define H_    512
#define G_    2048          // 4*H
#define M_    (B_*T_)       // 32768
#define NCTA_ 128
#define HB_   (H_*B_)

typedef unsigned long long ull;

// ---------------- packed f32x2 helpers (validated round 4) ----------------
__device__ __forceinline__ void ffma2(ull& acc, ull a, ull b) {
    asm("fma.rn.f32x2 %0, %1, %2, %0;" : "+l"(acc) : "l"(a), "l"(b));
}
__device__ __forceinline__ void fadd2(ull& acc, ull b) {
    asm("add.rn.f32x2 %0, %0, %1;" : "+l"(acc) : "l"(b));
}
__device__ __forceinline__ ull pack2(float lo, float hi) {
    ull r; asm("mov.b64 %0, {%1, %2};" : "=l"(r) : "f"(lo), "f"(hi)); return r;
}
__device__ __forceinline__ void unpack2(ull v, float& lo, float& hi) {
    asm("mov.b64 {%0, %1}, %2;" : "=f"(lo), "=f"(hi) : "l"(v));
}

// ---------------- cp.async helpers ----------------
__device__ __forceinline__ void cp_async16(void* smem_dst, const void* gsrc) {
    unsigned s = (unsigned)__cvta_generic_to_shared(smem_dst);
    asm volatile("cp.async.cg.shared.global [%0], [%1], 16;" :: "r"(s), "l"(gsrc));
}
__device__ __forceinline__ void cp_commit() {
    asm volatile("cp.async.commit_group;");
}
template <int N>
__device__ __forceinline__ void cp_wait() {
    asm volatile("cp.async.wait_group %0;" :: "n"(N));
}

// ---------------- scratch (static device allocations only) ----------------
__device__ float g_xT[(size_t)F_ * M_];       //   8 MB : x transposed [F][M]
__device__ float g_xw[(size_t)M_ * G_];       // 256 MB : xW1 (+bias) [M][G]
__device__ float g_h1bufT[2 * HB_];           // double-buffered h1, transposed [k][b]
__device__ float g_h2bufT[2 * HB_];           // double-buffered h2, transposed [k][b]
__device__ unsigned g_cnt8[8 * 32];
__device__ unsigned g_gen8[8 * 32];
__device__ unsigned g_done8;

// acquire load (plain load — same-address polls broadcast, no L2 serialization)
__device__ __forceinline__ unsigned ld_acq(const unsigned* p) {
    unsigned v;
    asm volatile("ld.acquire.gpu.global.u32 %0, [%1];" : "=r"(v) : "l"(p));
    return v;
}

// ---------------- grid-wide barrier: sharded arrivals + load-poll release ----------------
__device__ __forceinline__ void grid_barrier()
{
    __syncthreads();
    if (threadIdx.x == 0) {
        const unsigned lane = blockIdx.x & 7u;          // 16 CTAs per lane
        unsigned* cntp = &g_cnt8[lane * 32];
        unsigned* genp = &g_gen8[lane * 32];
        __threadfence();
        unsigned gen = ld_acq(genp);
        unsigned arrived = atomicAdd(cntp, 1u);
        if (arrived == 15u) {                            // lane closer
            atomicExch(cntp, 0u);
            unsigned d = atomicAdd(&g_done8, 1u);
            if (d == 7u) {                               // final closer: release all
                atomicExch(&g_done8, 0u);
                __threadfence();
#pragma unroll
                for (int l = 0; l < 8; l++)
                    atomicAdd(&g_gen8[l * 32], 1u);
            } else {
                while (ld_acq(genp) == gen) { __nanosleep(32); }
            }
        } else {
            while (ld_acq(genp) == gen) { __nanosleep(32); }
        }
        __threadfence();
    }
    __syncthreads();
}

// ---------------- x transpose: x[M][F] -> xT[F][M] ----------------
__global__ void __launch_bounds__(256) transpose_x(const float* __restrict__ x,
                                                   float* __restrict__ xT)
{
    __shared__ float tile[32][33];
    const int m0 = blockIdx.x * 32;
    const int f0 = blockIdx.y * 32;
    const int tx = threadIdx.x, ty = threadIdx.y;
#pragma unroll
    for (int i = 0; i < 32; i += 8)
        tile[ty + i][tx] = x[(size_t)(m0 + ty + i) * F_ + f0 + tx];
    __syncthreads();
#pragma unroll
    for (int i = 0; i < 32; i += 8)
        xT[(size_t)(f0 + ty + i) * M_ + m0 + tx] = tile[tx][ty + i];
}

// ---------------- GEMM (FFMA2, proven) — GEMM1: xW1 ----------------
__global__ void __launch_bounds__(256) gemm_atb(const float* __restrict__ AT,
                                                const float* __restrict__ Bm,
                                                const float* __restrict__ bias,
                                                float* __restrict__ C,
                                                int M, int N, int K)
{
    __shared__ float As[2][16 * 64];
    __shared__ float Bs[2][16 * 64];
    const int tid = threadIdx.x;
    const int tx = tid & 15, ty = tid >> 4;
    const int m0 = blockIdx.y * 64, n0 = blockIdx.x * 64;
    const int lr = tid >> 4, lc4 = (tid & 15) * 4;

    const float* ap = AT + (size_t)lr * M + m0 + lc4;
    const float* bp = Bm + (size_t)lr * N + n0 + lc4;
    float4 aReg = *(const float4*)ap;
    float4 bReg = *(const float4*)bp;

    ull accP[4][2];
#pragma unroll
    for (int i = 0; i < 4; i++) { accP[i][0] = 0ull; accP[i][1] = 0ull; }

    const int NT = K >> 4;
    for (int kt = 0; kt < NT; kt++) {
        const int cur = kt & 1;
        *(float4*)&As[cur][lr * 64 + lc4] = aReg;
        *(float4*)&Bs[cur][lr * 64 + lc4] = bReg;
        __syncthreads();
        if (kt + 1 < NT) {
            aReg = *(const float4*)(ap + (size_t)(kt + 1) * 16 * M);
            bReg = *(const float4*)(bp + (size_t)(kt + 1) * 16 * N);
        }
#pragma unroll
        for (int kk = 0; kk < 16; kk++) {
            float4 a = *(const float4*)&As[cur][kk * 64 + ty * 4];
            ulonglong2 bv = *(const ulonglong2*)&Bs[cur][kk * 64 + tx * 4];
            ull a0 = pack2(a.x, a.x);
            ull a1 = pack2(a.y, a.y);
            ull a2 = pack2(a.z, a.z);
            ull a3 = pack2(a.w, a.w);
            ffma2(accP[0][0], a0, bv.x); ffma2(accP[0][1], a0, bv.y);
            ffma2(accP[1][0], a1, bv.x); ffma2(accP[1][1], a1, bv.y);
            ffma2(accP[2][0], a2, bv.x); ffma2(accP[2][1], a2, bv.y);
            ffma2(accP[3][0], a3, bv.x); ffma2(accP[3][1], a3, bv.y);
        }
    }
    float acc[4][4];
#pragma unroll
    for (int i = 0; i < 4; i++) {
        unpack2(accP[i][0], acc[i][0], acc[i][1]);
        unpack2(accP[i][1], acc[i][2], acc[i][3]);
    }
    float4 bv = *(const float4*)(bias + n0 + tx * 4);
#pragma unroll
    for (int i = 0; i < 4; i++) {
        float4 o;
        o.x = acc[i][0] + bv.x;
        o.y = acc[i][1] + bv.y;
        o.z = acc[i][2] + bv.z;
        o.w = acc[i][3] + bv.w;
        *(float4*)&C[(size_t)(m0 + ty * 4 + i) * N + n0 + tx * 4] = o;
    }
}

// ---------------- fused two-layer persistent LSTM, pipelined across layers ----------------
// 128 CTAs, 256 threads. CTA owns hidden cols hc0..hc0+3 of BOTH layers.
// Global step s (0..512): layer1 computes t=s (s<512), layer2 computes t=s-1 (s>=1).
//   z1_s   = xw1[:,s,:]      + h1[s-1] @ Wh1
//   z2_s-1 = h1[s-1] @ Wi2 + b2 + h2[s-2] @ Wh2
// One staging of h1[s-1] feeds both z1 and z2's Wi2 term; then h2[s-2] staged for Wh2.
__global__ void __launch_bounds__(256, 1) lstm_fused(const float* __restrict__ xw,
                                                     const float* __restrict__ Wh1,
                                                     const float* __restrict__ Wi2,
                                                     const float* __restrict__ Wh2,
                                                     const float* __restrict__ b2)
{
    extern __shared__ float sm[];
    float* w1_s  = sm;                  // Wh1 slice [512][16]  (8192 floats)
    float* wi2_s = sm + 8192;           // Wi2 slice [512][16]
    float* wh2_s = sm + 16384;          // Wh2 slice [512][16]
    float* h_s   = sm + 24576;          // 3-slot ring, 128k x 64b per slot (24576 floats)
    float* redZ1 = sm + 49152;          // 3*64*16 = 3072
    float* redZ2 = sm + 52224;          // 3072
    float* z1_s  = sm + 55296;          // 64*16
    float* z2_s  = sm + 56320;          // 64*16
    float* c1_s  = sm + 57344;          // 256
    float* c2_s  = sm + 57600;          // 256
    float* b2_s  = sm + 57856;          // 16   (total 57872 floats = 231488 B)

    const int tid = threadIdx.x;
    const int hc0 = blockIdx.x * 4;

    // load weight slices: w[k][g*4+c] = W[k*G + g*512 + hc0 + c]
    for (int i = tid; i < 512 * 4; i += 256) {
        int k = i >> 2, g = i & 3;
        size_t go = (size_t)k * G_ + g * H_ + hc0;
        *(float4*)(w1_s  + k * 16 + g * 4) = *(const float4*)(Wh1 + go);
        *(float4*)(wi2_s + k * 16 + g * 4) = *(const float4*)(Wi2 + go);
        *(float4*)(wh2_s + k * 16 + g * 4) = *(const float4*)(Wh2 + go);
    }
    if (tid < 16) b2_s[tid] = b2[(tid >> 2) * H_ + hc0 + (tid & 3)];
    c1_s[tid] = 0.f;
    c2_s[tid] = 0.f;
    // zero both parities of this CTA's h1/h2 slices
    for (int i = tid; i < 512; i += 256) {
        int bufi = i >> 8, rem = i & 255;
        int c = rem >> 6, b = rem & 63;
        g_h1bufT[bufi * HB_ + (hc0 + c) * B_ + b] = 0.f;
        g_h2bufT[bufi * HB_ + (hc0 + c) * B_ + b] = 0.f;
    }
    __threadfence();
    grid_barrier();

    const int q  = tid >> 6;   // 4-way k-split group
    const int r  = tid & 63;
    const int rg = r & 15;     // batch rows 4*rg .. 4*rg+3
    const int cg = r >> 4;     // gate index 0..3

    for (int s = 0; s <= T_; s++) {
        // h1[s-1] lives in buf[(s-1)&1] = buf[(s+1)&1]; h2[s-2] in buf2[s&1]
        const float4* h1src4 = (const float4*)(g_h1bufT + ((s + 1) & 1) * HB_);
        const float4* h2src4 = (const float4*)(g_h2bufT + (s & 1) * HB_);
        float* h1dst = g_h1bufT + (s & 1) * HB_;
        float* h2dst = g_h2bufT + ((s + 1) & 1) * HB_;   // (s-1)&1 == (s+1)&1

        // prefetch xw1 for layer1 step t=s (q==0 threads, guarded)
        float4 xv0, xv1, xv2, xv3;
        xv0 = xv1 = xv2 = xv3 = make_float4(0.f, 0.f, 0.f, 0.f);
        if (q == 0 && s < T_) {
            const float* xp = xw + (size_t)(4 * rg * T_ + s) * G_ + cg * H_ + hc0;
            xv0 = *(const float4*)(xp);
            xv1 = *(const float4*)(xp + (size_t)T_ * G_);
            xv2 = *(const float4*)(xp + (size_t)2 * T_ * G_);
            xv3 = *(const float4*)(xp + (size_t)3 * T_ * G_);
        }

        // chunk issue: chunks 0-3 = h1 (128 k-rows each), chunks 4-7 = h2
        auto issue_chunk = [&](int cc) {
            const float4* src = (cc < 4) ? (h1src4 + cc * 2048)
                                         : (h2src4 + (cc - 4) * 2048);
            float* dst = h_s + (cc % 3) * 8192;
#pragma unroll
            for (int j = 0; j < 8; j++) {
                int idx = tid + j * 256;
                cp_async16(dst + idx * 4, src + idx);
            }
            cp_commit();
        };

        issue_chunk(0);

        ull accZ1[4][2], accZ2[4][2];
#pragma unroll
        for (int i = 0; i < 4; i++) {
            accZ1[i][0] = accZ1[i][1] = 0ull;
            accZ2[i][0] = accZ2[i][1] = 0ull;
        }

#pragma unroll
        for (int cc = 0; cc < 8; cc++) {
            if (cc < 7) { issue_chunk(cc + 1); cp_wait<1>(); }
            else        { cp_wait<0>(); }
            __syncthreads();

            const float* hp = h_s + (cc % 3) * 8192 + (q * 32) * 64 + 4 * rg;
            if (cc < 4) {
                const int kb = (cc * 128 + q * 32) * 16 + 4 * cg;
                const float* w1p = w1_s  + kb;
                const float* w2p = wi2_s + kb;
#pragma unroll 8
                for (int kk = 0; kk < 32; kk++) {
                    float4 hv = *(const float4*)(hp + kk * 64);
                    ulonglong2 wa = *(const ulonglong2*)(w1p + kk * 16);
                    ulonglong2 wb = *(const ulonglong2*)(w2p + kk * 16);
                    ull h0 = pack2(hv.x, hv.x);
                    ull h1 = pack2(hv.y, hv.y);
                    ull h2 = pack2(hv.z, hv.z);
                    ull h3 = pack2(hv.w, hv.w);
                    // hv rows are k, k+1, k+2, k+3?  No: hv = h[k][4 batches rg*4..].
                    // Same semantics as proven kernel: 4 batch rows, broadcast k.
                    ffma2(accZ1[0][0], h0, wa.x); ffma2(accZ1[0][1], h0, wa.y);
                    ffma2(accZ1[1][0], h1, wa.x); ffma2(accZ1[1][1], h1, wa.y);
                    ffma2(accZ1[2][0], h2, wa.x); ffma2(accZ1[2][1], h2, wa.y);
                    ffma2(accZ1[3][0], h3, wa.x); ffma2(accZ1[3][1], h3, wa.y);
                    ffma2(accZ2[0][0], h0, wb.x); ffma2(accZ2[0][1], h0, wb.y);
                    ffma2(accZ2[1][0], h1, wb.x); ffma2(accZ2[1][1], h1, wb.y);
                    ffma2(accZ2[2][0], h2, wb.x); ffma2(accZ2[2][1], h2, wb.y);
                    ffma2(accZ2[3][0], h3, wb.x); ffma2(accZ2[3][1], h3, wb.y);
                }
            } else {
                const float* w3p = wh2_s + ((cc - 4) * 128 + q * 32) * 16 + 4 * cg;
#pragma unroll 8
                for (int kk = 0; kk < 32; kk++) {
                    float4 hv = *(const float4*)(hp + kk * 64);
                    ulonglong2 wc = *(const ulonglong2*)(w3p + kk * 16);
                    ull h0 = pack2(hv.x, hv.x);
                    ull h1 = pack2(hv.y, hv.y);
                    ull h2 = pack2(hv.z, hv.z);
                    ull h3 = pack2(hv.w, hv.w);
                    ffma2(accZ2[0][0], h0, wc.x); ffma2(accZ2[0][1], h0, wc.y);
                    ffma2(accZ2[1][0], h1, wc.x); ffma2(accZ2[1][1], h1, wc.y);
                    ffma2(accZ2[2][0], h2, wc.x); ffma2(accZ2[2][1], h2, wc.y);
                    ffma2(accZ2[3][0], h3, wc.x); ffma2(accZ2[3][1], h3, wc.y);
                }
            }
        }

        // ---- dual k-split reduction: q0 reduces z1, q1 reduces z2 ----
        if (q != 0) {
            float* rp = redZ1 + ((q - 1) * 64 + r) * 16;
#pragma unroll
            for (int i = 0; i < 4; i++) {
                *(ull*)(rp + i * 4)     = accZ1[i][0];
                *(ull*)(rp + i * 4 + 2) = accZ1[i][1];
            }
        }
        if (q != 1) {
            int m = (q == 0) ? 0 : q - 1;
            float* rp = redZ2 + (m * 64 + r) * 16;
#pragma unroll
            for (int i = 0; i < 4; i++) {
                *(ull*)(rp + i * 4)     = accZ2[i][0];
                *(ull*)(rp + i * 4 + 2) = accZ2[i][1];
            }
        }
        __syncthreads();

        if (q == 0 && s < T_) {
#pragma unroll
            for (int qq = 0; qq < 3; qq++) {
                const float* rp = redZ1 + (qq * 64 + r) * 16;
#pragma unroll
                for (int i = 0; i < 4; i++) {
                    fadd2(accZ1[i][0], *(const ull*)(rp + i * 4));
                    fadd2(accZ1[i][1], *(const ull*)(rp + i * 4 + 2));
                }
            }
            float a[4][4];
#pragma unroll
            for (int i = 0; i < 4; i++) {
                unpack2(accZ1[i][0], a[i][0], a[i][1]);
                unpack2(accZ1[i][1], a[i][2], a[i][3]);
            }
            float4 xv[4] = {xv0, xv1, xv2, xv3};
#pragma unroll
            for (int i = 0; i < 4; i++) {
                const float* xf = (const float*)&xv[i];
#pragma unroll
                for (int j = 0; j < 4; j++)
                    z1_s[(4 * rg + i) * 16 + 4 * cg + j] = a[i][j] + xf[j];
            }
        }
        if (q == 1 && s >= 1) {
#pragma unroll
            for (int qq = 0; qq < 3; qq++) {
                const float* rp = redZ2 + (qq * 64 + r) * 16;
#pragma unroll
                for (int i = 0; i < 4; i++) {
                    fadd2(accZ2[i][0], *(const ull*)(rp + i * 4));
                    fadd2(accZ2[i][1], *(const ull*)(rp + i * 4 + 2));
                }
            }
            float a[4][4];
#pragma unroll
            for (int i = 0; i < 4; i++) {
                unpack2(accZ2[i][0], a[i][0], a[i][1]);
                unpack2(accZ2[i][1], a[i][2], a[i][3]);
            }
#pragma unroll
            for (int i = 0; i < 4; i++)
#pragma unroll
                for (int j = 0; j < 4; j++)
                    z2_s[(4 * rg + i) * 16 + 4 * cg + j] = a[i][j];
        }
        __syncthreads();

        // ---- state updates: thread -> (b = tid>>2, c = tid&3) ----
        {
            const int b = tid >> 2, c = tid & 3;
            if (s < T_) {
                float zi = z1_s[b * 16 + 0  + c];
                float zf = z1_s[b * 16 + 4  + c];
                float zg = z1_s[b * 16 + 8  + c];
                float zo = z1_s[b * 16 + 12 + c];
                float ig = 1.f / (1.f + expf(-zi));
                float fg = 1.f / (1.f + expf(-zf));
                float gg = tanhf(zg);
                float og = 1.f / (1.f + expf(-zo));
                float cc1 = fmaf(fg, c1_s[tid], ig * gg);
                c1_s[tid] = cc1;
                h1dst[(hc0 + c) * B_ + b] = og * tanhf(cc1);
            }
            if (s >= 1) {
                float zi = z2_s[b * 16 + 0  + c] + b2_s[0  + c];
                float zf = z2_s[b * 16 + 4  + c] + b2_s[4  + c];
                float zg = z2_s[b * 16 + 8  + c] + b2_s[8  + c];
                float zo = z2_s[b * 16 + 12 + c] + b2_s[12 + c];
                float ig = 1.f / (1.f + expf(-zi));
                float fg = 1.f / (1.f + expf(-zf));
                float gg = tanhf(zg);
                float og = 1.f / (1.f + expf(-zo));
                float cc2 = fmaf(fg, c2_s[tid], ig * gg);
                c2_s[tid] = cc2;
                h2dst[(hc0 + c) * B_ + b] = og * tanhf(cc2);
            }
        }
        grid_barrier();
    }
}

// ---------------- head: out[b] = relu(relu(h@Wd1 + bd1) @ Wd2 + bd2) ----------------
__global__ void __launch_bounds__(256) head_kernel(const float* __restrict__ Wd1,
                                                   const float* __restrict__ bd1,
                                                   const float* __restrict__ Wd2,
                                                   const float* __restrict__ bd2,
                                                   float* __restrict__ out)
{
    const int b = blockIdx.x;
    const int j = threadIdx.x;
    const float* hT = g_h2bufT + HB_;          // h2[511] written at s=512 into buf2[1]
    float acc = 0.f;
#pragma unroll 8
    for (int k = 0; k < H_; k++)
        acc = fmaf(hT[k * B_ + b], Wd1[k * (H_ / 2) + j], acc);
    float t1 = fmaxf(acc + bd1[j], 0.f);
    float p  = t1 * Wd2[j];
    __shared__ float s[256];
    s[j] = p;
    __syncthreads();
    for (int off = 128; off; off >>= 1) {
        if (j < off) s[j] += s[j + off];
        __syncthreads();
    }
    if (j == 0) out[b] = fmaxf(s[0] + bd2[0], 0.f);
}

// ---------------- launch ----------------
extern "C" void kernel_launch(void* const* d_in, const int* in_sizes, int n_in,
                              void* d_out, int out_size)
{
    (void)in_sizes; (void)n_in; (void)out_size;
    const float* x   = (const float*)d_in[0];
    const float* Wi1 = (const float*)d_in[2];
    const float* Wh1 = (const float*)d_in[3];
    const float* b1  = (const float*)d_in[4];
    const float* Wi2 = (const float*)d_in[5];
    const float* Wh2 = (const float*)d_in[6];
    const float* b2  = (const float*)d_in[7];
    const float* Wd1 = (const float*)d_in[8];
    const float* bd1 = (const float*)d_in[9];
    const float* Wd2 = (const float*)d_in[10];
    const float* bd2 = (const float*)d_in[11];
    float* out = (float*)d_out;

    float *xT, *xwb;
    cudaGetSymbolAddress((void**)&xT,  g_xT);
    cudaGetSymbolAddress((void**)&xwb, g_xw);

    const size_t smem = 57872 * sizeof(float);   // 231488 B (<= 232448 opt-in)
    cudaFuncSetAttribute(lstm_fused,
                         cudaFuncAttributeMaxDynamicSharedMemorySize, (int)smem);

    transpose_x<<<dim3(1024, 2), dim3(32, 8)>>>(x, xT);
    gemm_atb<<<dim3(G_ / 64, M_ / 64), 256>>>(xT, Wi1, b1, xwb, M_, G_, F_);
    lstm_fused<<<NCTA_, 256, smem>>>(xwb, Wh1, Wi2, Wh2, b2);
    head_kernel<<<B_, 256>>>(Wd1, bd1, Wd2, bd2, out);
}

// round 12
// speedup vs baseline: 4.4572x; 1.4154x over previous
#include <cuda_runtime.h>
#include <cuda_bf16.h>
#include <math.h>

#define B_    64
#define T_    512
#define F_    64
#define H_    512
#define G_    2048          // 4*H
#define M_    (B_*T_)       // 32768
#define NCTA_ 128
#define HB_   (H_*B_)       // 32768

typedef unsigned long long ull;

// ---------------- packed f32x2 helpers (for gemm_atb) ----------------
__device__ __forceinline__ void ffma2(ull& acc, ull a, ull b) {
    asm("fma.rn.f32x2 %0, %1, %2, %0;" : "+l"(acc) : "l"(a), "l"(b));
}
__device__ __forceinline__ ull pack2(float lo, float hi) {
    ull r; asm("mov.b64 %0, {%1, %2};" : "=l"(r) : "f"(lo), "f"(hi)); return r;
}
__device__ __forceinline__ void unpack2(ull v, float& lo, float& hi) {
    asm("mov.b64 {%0, %1}, %2;" : "=f"(lo), "=f"(hi) : "l"(v));
}

// ---------------- cp.async helpers ----------------
__device__ __forceinline__ void cp_async16(void* smem_dst, const void* gsrc) {
    unsigned s = (unsigned)__cvta_generic_to_shared(smem_dst);
    asm volatile("cp.async.cg.shared.global [%0], [%1], 16;" :: "r"(s), "l"(gsrc));
}
__device__ __forceinline__ void cp_commit() {
    asm volatile("cp.async.commit_group;");
}
template <int N>
__device__ __forceinline__ void cp_wait() {
    asm volatile("cp.async.wait_group %0;" :: "n"(N));
}

// ---------------- HMMA helpers (baseline PTX, proven round 9) ----------------
#define SWZ128(x) ((x) ^ (((x) >> 3) & 0x70))
#define SWZW(x)   ((x) ^ (((x) >> 6) & 0x70))      // for 1024B-row weight tiles

__device__ __forceinline__ void ldsm_x4(unsigned& r0, unsigned& r1, unsigned& r2, unsigned& r3,
                                        unsigned addr) {
    asm volatile("ldmatrix.sync.aligned.m8n8.x4.shared.b16 {%0,%1,%2,%3}, [%4];"
                 : "=r"(r0), "=r"(r1), "=r"(r2), "=r"(r3) : "r"(addr));
}
__device__ __forceinline__ void ldsm_x2(unsigned& r0, unsigned& r1, unsigned addr) {
    asm volatile("ldmatrix.sync.aligned.m8n8.x2.shared.b16 {%0,%1}, [%2];"
                 : "=r"(r0), "=r"(r1) : "r"(addr));
}
__device__ __forceinline__ void mma_bf16(float* c, const unsigned* a, const unsigned* b) {
    asm volatile("mma.sync.aligned.m16n8k16.row.col.f32.bf16.bf16.f32 "
                 "{%0,%1,%2,%3}, {%4,%5,%6,%7}, {%8,%9}, {%0,%1,%2,%3};"
                 : "+f"(c[0]), "+f"(c[1]), "+f"(c[2]), "+f"(c[3])
                 : "r"(a[0]), "r"(a[1]), "r"(a[2]), "r"(a[3]), "r"(b[0]), "r"(b[1]));
}

// ---------------- scratch (static device allocations only) ----------------
__device__ float g_xT[(size_t)F_ * M_];       //   8 MB : x transposed [F][M]
__device__ float g_xw[(size_t)M_ * G_];       // 256 MB : xW1 (+b1) [M][G]
__device__ float g_h2bufT[2 * HB_];           // fp32 h2 (for head), [buf][k][b]
__device__ __nv_bfloat16 g_h1hi[2 * HB_];     // split-bf16 h buffers, [buf][b][k]
__device__ __nv_bfloat16 g_h1lo[2 * HB_];
__device__ __nv_bfloat16 g_h2hi[2 * HB_];
__device__ __nv_bfloat16 g_h2lo[2 * HB_];
__device__ unsigned g_cnt8[8 * 32];
__device__ unsigned g_gen8[8 * 32];
__device__ unsigned g_done8;

// ---------------- smem layout (bytes) for lstm_fused ----------------
#define SM_W1HI   0
#define SM_W1LO   16384
#define SM_WI2HI  32768
#define SM_WI2LO  49152
#define SM_WH2HI  65536
#define SM_WH2LO  81920
#define SM_RING   98304      // 4 slots x 16384 (hi 8192 | lo 8192)
#define SM_RED    163840     // 24 tiles x 256 floats = 24576 B
#define SM_C1     188416     // 256 floats
#define SM_C2     189440
#define SM_B2     190464     // 16 floats
#define SM_TOTAL  190528

// acquire load
__device__ __forceinline__ unsigned ld_acq(const unsigned* p) {
    unsigned v;
    asm volatile("ld.acquire.gpu.global.u32 %0, [%1];" : "=r"(v) : "l"(p));
    return v;
}

// ---------------- grid-wide barrier (proven rounds 6-11) ----------------
__device__ __forceinline__ void grid_barrier()
{
    __syncthreads();
    if (threadIdx.x == 0) {
        const unsigned lane = blockIdx.x & 7u;
        unsigned* cntp = &g_cnt8[lane * 32];
        unsigned* genp = &g_gen8[lane * 32];
        __threadfence();
        unsigned gen = ld_acq(genp);
        unsigned arrived = atomicAdd(cntp, 1u);
        if (arrived == 15u) {
            atomicExch(cntp, 0u);
            unsigned d = atomicAdd(&g_done8, 1u);
            if (d == 7u) {
                atomicExch(&g_done8, 0u);
                __threadfence();
#pragma unroll
                for (int l = 0; l < 8; l++)
                    atomicAdd(&g_gen8[l * 32], 1u);
            } else {
                while (ld_acq(genp) == gen) { __nanosleep(32); }
            }
        } else {
            while (ld_acq(genp) == gen) { __nanosleep(32); }
        }
        __threadfence();
    }
    __syncthreads();
}

// ---------------- x transpose ----------------
__global__ void __launch_bounds__(256) transpose_x(const float* __restrict__ x,
                                                   float* __restrict__ xT)
{
    __shared__ float tile[32][33];
    const int m0 = blockIdx.x * 32;
    const int f0 = blockIdx.y * 32;
    const int tx = threadIdx.x, ty = threadIdx.y;
#pragma unroll
    for (int i = 0; i < 32; i += 8)
        tile[ty + i][tx] = x[(size_t)(m0 + ty + i) * F_ + f0 + tx];
    __syncthreads();
#pragma unroll
    for (int i = 0; i < 32; i += 8)
        xT[(size_t)(f0 + ty + i) * M_ + m0 + tx] = tile[tx][ty + i];
}

// ---------------- GEMM (FFMA2, proven) — GEMM1: xW1 ----------------
__global__ void __launch_bounds__(256) gemm_atb(const float* __restrict__ AT,
                                                const float* __restrict__ Bm,
                                                const float* __restrict__ bias,
                                                float* __restrict__ C,
                                                int M, int N, int K)
{
    __shared__ float As[2][16 * 64];
    __shared__ float Bs[2][16 * 64];
    const int tid = threadIdx.x;
    const int tx = tid & 15, ty = tid >> 4;
    const int m0 = blockIdx.y * 64, n0 = blockIdx.x * 64;
    const int lr = tid >> 4, lc4 = (tid & 15) * 4;

    const float* ap = AT + (size_t)lr * M + m0 + lc4;
    const float* bp = Bm + (size_t)lr * N + n0 + lc4;
    float4 aReg = *(const float4*)ap;
    float4 bReg = *(const float4*)bp;

    ull accP[4][2];
#pragma unroll
    for (int i = 0; i < 4; i++) { accP[i][0] = 0ull; accP[i][1] = 0ull; }

    const int NT = K >> 4;
    for (int kt = 0; kt < NT; kt++) {
        const int cur = kt & 1;
        *(float4*)&As[cur][lr * 64 + lc4] = aReg;
        *(float4*)&Bs[cur][lr * 64 + lc4] = bReg;
        __syncthreads();
        if (kt + 1 < NT) {
            aReg = *(const float4*)(ap + (size_t)(kt + 1) * 16 * M);
            bReg = *(const float4*)(bp + (size_t)(kt + 1) * 16 * N);
        }
#pragma unroll
        for (int kk = 0; kk < 16; kk++) {
            float4 a = *(const float4*)&As[cur][kk * 64 + ty * 4];
            ulonglong2 bv = *(const ulonglong2*)&Bs[cur][kk * 64 + tx * 4];
            ull a0 = pack2(a.x, a.x);
            ull a1 = pack2(a.y, a.y);
            ull a2 = pack2(a.z, a.z);
            ull a3 = pack2(a.w, a.w);
            ffma2(accP[0][0], a0, bv.x); ffma2(accP[0][1], a0, bv.y);
            ffma2(accP[1][0], a1, bv.x); ffma2(accP[1][1], a1, bv.y);
            ffma2(accP[2][0], a2, bv.x); ffma2(accP[2][1], a2, bv.y);
            ffma2(accP[3][0], a3, bv.x); ffma2(accP[3][1], a3, bv.y);
        }
    }
    float acc[4][4];
#pragma unroll
    for (int i = 0; i < 4; i++) {
        unpack2(accP[i][0], acc[i][0], acc[i][1]);
        unpack2(accP[i][1], acc[i][2], acc[i][3]);
    }
    float4 bv = *(const float4*)(bias + n0 + tx * 4);
#pragma unroll
    for (int i = 0; i < 4; i++) {
        float4 o;
        o.x = acc[i][0] + bv.x;
        o.y = acc[i][1] + bv.y;
        o.z = acc[i][2] + bv.z;
        o.w = acc[i][3] + bv.w;
        *(float4*)&C[(size_t)(m0 + ty * 4 + i) * N + n0 + tx * 4] = o;
    }
}

// ---------------- per-chunk MMA body (round-9 proven fragment geometry) ----------------
__device__ __forceinline__ void mma_chunk(float acc[2][4], unsigned sbase,
                                          unsigned slot, unsigned wbase,
                                          int mt, int kk0,
                                          int aRow, int aKof, int bRow, int bKof)
{
#pragma unroll
    for (int ks = 0; ks < 4; ks++) {
        unsigned ah[4], al[4];
        unsigned aoff = SWZ128((unsigned)((mt * 16 + aRow) * 128 + (ks * 16 + aKof) * 2));
        ldsm_x4(ah[0], ah[1], ah[2], ah[3], slot + aoff);
        ldsm_x4(al[0], al[1], al[2], al[3], slot + 8192 + aoff);
        int kk = kk0 + ks * 16;
#pragma unroll
        for (int nt = 0; nt < 2; nt++) {
            unsigned bh[2], bl[2];
            unsigned boff = SWZW((unsigned)((nt * 8 + bRow) * 1024 + (kk + bKof) * 2));
            ldsm_x2(bh[0], bh[1], sbase + wbase + boff);
            ldsm_x2(bl[0], bl[1], sbase + wbase + 16384 + boff);
            mma_bf16(acc[nt], ah, bh);
            mma_bf16(acc[nt], ah, bl);
            mma_bf16(acc[nt], al, bh);
        }
    }
}

// ---------------- fused two-layer persistent LSTM — tensor-core matmuls ----------------
// 128 CTAs, 256 threads. CTA owns hidden cols hc0..hc0+3 of both layers.
// Step s: z1(t=s) = xw + h1[s-1]@Wh1 ; z2(t=s-1) = h1[s-1]@Wi2 + h2[s-2]@Wh2 + b2.
// All matmuls via mma.sync bf16 with split-bf16 x3, fp32 accumulate.
__global__ void __launch_bounds__(256, 1) lstm_fused(const float* __restrict__ xw,
                                                     const float* __restrict__ Wh1,
                                                     const float* __restrict__ Wi2,
                                                     const float* __restrict__ Wh2,
                                                     const float* __restrict__ b2)
{
    extern __shared__ char smc[];
    float* red  = (float*)(smc + SM_RED);
    float* c1_s = (float*)(smc + SM_C1);
    float* c2_s = (float*)(smc + SM_C2);
    float* b2_s = (float*)(smc + SM_B2);
    const unsigned sbase = (unsigned)__cvta_generic_to_shared(smc);

    const int tid  = threadIdx.x;
    const int wid  = tid >> 5, lane = tid & 31;
    const int grp  = lane >> 2, tig = lane & 3;
    const int aRow = lane & 15;
    const int aKof = (lane >> 4) << 3;
    const int bRow = lane & 7;
    const int bKof = ((lane >> 3) & 1) << 3;
    const int hc0  = blockIdx.x * 4;

    // ---- one-time init: weights -> smem bf16 hi/lo, [col][k] with SWZW ----
    for (int i = tid; i < 16 * 512; i += 256) {
        int k = i >> 4, col = i & 15;
        size_t go = (size_t)k * G_ + (col >> 2) * H_ + hc0 + (col & 3);
        unsigned off = SWZW((unsigned)(col * 1024 + k * 2));
        float v; __nv_bfloat16 h;
        v = Wh1[go]; h = __float2bfloat16(v);
        *(__nv_bfloat16*)(smc + SM_W1HI + off) = h;
        *(__nv_bfloat16*)(smc + SM_W1LO + off) = __float2bfloat16(v - __bfloat162float(h));
        v = Wi2[go]; h = __float2bfloat16(v);
        *(__nv_bfloat16*)(smc + SM_WI2HI + off) = h;
        *(__nv_bfloat16*)(smc + SM_WI2LO + off) = __float2bfloat16(v - __bfloat162float(h));
        v = Wh2[go]; h = __float2bfloat16(v);
        *(__nv_bfloat16*)(smc + SM_WH2HI + off) = h;
        *(__nv_bfloat16*)(smc + SM_WH2LO + off) = __float2bfloat16(v - __bfloat162float(h));
    }
    if (tid < 16) b2_s[tid] = b2[(tid >> 2) * H_ + hc0 + (tid & 3)];
    c1_s[tid] = 0.f;
    c2_s[tid] = 0.f;
    // zero this CTA's h slices (both parities, all buffers)
    for (int i = tid; i < 512; i += 256) {
        int bufi = i >> 8, rem = i & 255;
        int c = rem >> 6, b = rem & 63;
        int idx = bufi * HB_ + b * 512 + hc0 + c;
        __nv_bfloat16 z = __float2bfloat16(0.f);
        g_h1hi[idx] = z; g_h1lo[idx] = z;
        g_h2hi[idx] = z; g_h2lo[idx] = z;
        g_h2bufT[bufi * HB_ + (hc0 + c) * B_ + b] = 0.f;
    }
    __threadfence();
    grid_barrier();

    const int bb = tid >> 2, cc_hid = tid & 3;     // reducer mapping: (batch, hidden)

    for (int s = 0; s <= T_; s++) {
        const int r1 = (s + 1) & 1;     // h1[s-1] parity
        const int r2 = s & 1;           // h2[s-2] parity
        const int w1 = s & 1;           // h1[s] write parity
        const int w2 = (s + 1) & 1;     // h2[s-1] write parity

        const __nv_bfloat16* h1hiR = g_h1hi + r1 * HB_;
        const __nv_bfloat16* h1loR = g_h1lo + r1 * HB_;
        const __nv_bfloat16* h2hiR = g_h2hi + r2 * HB_;
        const __nv_bfloat16* h2loR = g_h2lo + r2 * HB_;

        // xw prefetch (per reducer thread), guarded
        float xv[4] = {0.f, 0.f, 0.f, 0.f};
        if (s < T_) {
            size_t xb = (size_t)(bb * T_ + s) * G_ + hc0 + cc_hid;
#pragma unroll
            for (int g = 0; g < 4; g++) xv[g] = __ldg(xw + xb + g * H_);
        }

        // chunk staging: cc 0-7 = h1 (k0 = cc*64), 8-15 = h2
        auto issue_chunk = [&](int ci) {
            const __nv_bfloat16* hi; const __nv_bfloat16* lo; int k0;
            if (ci < 8) { hi = h1hiR; lo = h1loR; k0 = ci * 64; }
            else        { hi = h2hiR; lo = h2loR; k0 = (ci - 8) * 64; }
            char* dst = smc + SM_RING + (ci & 3) * 16384;
#pragma unroll
            for (int rep = 0; rep < 2; rep++) {
                int i = tid + rep * 256;
                int row = i >> 3, seg = i & 7;
                unsigned o = SWZ128((unsigned)(row * 128 + seg * 16));
                const __nv_bfloat16* src = hi + row * 512 + k0 + seg * 8;
                cp_async16(dst + o, src);
                cp_async16(dst + 8192 + o, lo + row * 512 + k0 + seg * 8);
            }
            cp_commit();
        };

        float accA[2][4], accB[2][4], accC[2][4];
#pragma unroll
        for (int i = 0; i < 2; i++)
#pragma unroll
            for (int e = 0; e < 4; e++) { accA[i][e] = 0.f; accB[i][e] = 0.f; accC[i][e] = 0.f; }

        issue_chunk(0);
        issue_chunk(1);

#pragma unroll
        for (int ck = 0; ck < 16; ck++) {
            if (ck <= 13)      { issue_chunk(ck + 2); cp_wait<2>(); }
            else if (ck == 14) { cp_wait<1>(); }
            else               { cp_wait<0>(); }
            __syncthreads();

            const unsigned slot = sbase + SM_RING + (unsigned)(ck & 3) * 16384;
            const int kk0 = (ck & 7) * 64;
            if (ck < 8) {
                if ((ck >> 2) == (wid >> 2))
                    mma_chunk(accA, sbase, slot, SM_W1HI,  wid & 3, kk0,
                              aRow, aKof, bRow, bKof);
                else
                    mma_chunk(accB, sbase, slot, SM_WI2HI, wid & 3, kk0,
                              aRow, aKof, bRow, bKof);
            } else if (((ck - 8) >> 2) == (wid & 1)) {
                mma_chunk(accC, sbase, slot, SM_WH2HI, wid >> 1, kk0,
                          aRow, aKof, bRow, bKof);
            }
        }

        // ---- write fp32 partial tiles to red ----
        auto store_tile = [&](int tileId, float acc[2][4]) {
            float* base = red + tileId * 256;
#pragma unroll
            for (int nt = 0; nt < 2; nt++) {
                int col = nt * 8 + tig * 2;
                base[grp * 16 + col]           = acc[nt][0];
                base[grp * 16 + col + 1]       = acc[nt][1];
                base[(grp + 8) * 16 + col]     = acc[nt][2];
                base[(grp + 8) * 16 + col + 1] = acc[nt][3];
            }
        };
        store_tile((wid & 3) * 2 + (wid >> 2), accA);                 // z1 tiles 0-7
        store_tile(8 + (wid & 3) * 2 + (1 - (wid >> 2)), accB);       // Wi2 tiles 8-15
        store_tile(16 + (wid >> 1) * 2 + (wid & 1), accC);            // Wh2 tiles 16-23
        __syncthreads();

        // ---- reduction + gates + state update: thread = (bb, cc_hid) ----
        {
            const int mt = bb >> 4, ri = bb & 15;
            const int rbase = ri * 16;
            if (s < T_) {
                float z[4];
#pragma unroll
                for (int g = 0; g < 4; g++) {
                    int col = g * 4 + cc_hid;
                    z[g] = xv[g] + red[(mt * 2) * 256 + rbase + col]
                                 + red[(mt * 2 + 1) * 256 + rbase + col];
                }
                float ig = 1.f / (1.f + expf(-z[0]));
                float fg = 1.f / (1.f + expf(-z[1]));
                float gg = tanhf(z[2]);
                float og = 1.f / (1.f + expf(-z[3]));
                float c1 = fmaf(fg, c1_s[tid], ig * gg);
                c1_s[tid] = c1;
                float h1 = og * tanhf(c1);
                __nv_bfloat16 hi = __float2bfloat16(h1);
                int idx = w1 * HB_ + bb * 512 + hc0 + cc_hid;
                g_h1hi[idx] = hi;
                g_h1lo[idx] = __float2bfloat16(h1 - __bfloat162float(hi));
            }
            if (s >= 1) {
                float z[4];
#pragma unroll
                for (int g = 0; g < 4; g++) {
                    int col = g * 4 + cc_hid;
                    z[g] = b2_s[col]
                         + red[(8 + mt * 2) * 256 + rbase + col]
                         + red[(8 + mt * 2 + 1) * 256 + rbase + col]
                         + red[(16 + mt * 2) * 256 + rbase + col]
                         + red[(16 + mt * 2 + 1) * 256 + rbase + col];
                }
                float ig = 1.f / (1.f + expf(-z[0]));
                float fg = 1.f / (1.f + expf(-z[1]));
                float gg = tanhf(z[2]);
                float og = 1.f / (1.f + expf(-z[3]));
                float c2 = fmaf(fg, c2_s[tid], ig * gg);
                c2_s[tid] = c2;
                float h2 = og * tanhf(c2);
                __nv_bfloat16 hi = __float2bfloat16(h2);
                int idx = w2 * HB_ + bb * 512 + hc0 + cc_hid;
                g_h2hi[idx] = hi;
                g_h2lo[idx] = __float2bfloat16(h2 - __bfloat162float(hi));
                g_h2bufT[w2 * HB_ + (hc0 + cc_hid) * B_ + bb] = h2;   // fp32 for head
            }
        }
        grid_barrier();
    }
}

// ---------------- head: out[b] = relu(relu(h@Wd1 + bd1) @ Wd2 + bd2) ----------------
__global__ void __launch_bounds__(256) head_kernel(const float* __restrict__ Wd1,
                                                   const float* __restrict__ bd1,
                                                   const float* __restrict__ Wd2,
                                                   const float* __restrict__ bd2,
                                                   float* __restrict__ out)
{
    const int b = blockIdx.x;
    const int j = threadIdx.x;
    const float* hT = g_h2bufT + HB_;          // h2[511] written at s=512 into parity 1
    float acc = 0.f;
#pragma unroll 8
    for (int k = 0; k < H_; k++)
        acc = fmaf(hT[k * B_ + b], Wd1[k * (H_ / 2) + j], acc);
    float t1 = fmaxf(acc + bd1[j], 0.f);
    float p  = t1 * Wd2[j];
    __shared__ float s[256];
    s[j] = p;
    __syncthreads();
    for (int off = 128; off; off >>= 1) {
        if (j < off) s[j] += s[j + off];
        __syncthreads();
    }
    if (j == 0) out[b] = fmaxf(s[0] + bd2[0], 0.f);
}

// ---------------- launch ----------------
extern "C" void kernel_launch(void* const* d_in, const int* in_sizes, int n_in,
                              void* d_out, int out_size)
{
    (void)in_sizes; (void)n_in; (void)out_size;
    const float* x   = (const float*)d_in[0];
    const float* Wi1 = (const float*)d_in[2];
    const float* Wh1 = (const float*)d_in[3];
    const float* b1  = (const float*)d_in[4];
    const float* Wi2 = (const float*)d_in[5];
    const float* Wh2 = (const float*)d_in[6];
    const float* b2  = (const float*)d_in[7];
    const float* Wd1 = (const float*)d_in[8];
    const float* bd1 = (const float*)d_in[9];
    const float* Wd2 = (const float*)d_in[10];
    const float* bd2 = (const float*)d_in[11];
    float* out = (float*)d_out;

    float *xT, *xwb;
    cudaGetSymbolAddress((void**)&xT,  g_xT);
    cudaGetSymbolAddress((void**)&xwb, g_xw);

    cudaFuncSetAttribute(lstm_fused,
                         cudaFuncAttributeMaxDynamicSharedMemorySize, SM_TOTAL);

    transpose_x<<<dim3(1024, 2), dim3(32, 8)>>>(x, xT);
    gemm_atb<<<dim3(G_ / 64, M_ / 64), 256>>>(xT, Wi1, b1, xwb, M_, G_, F_);
    lstm_fused<<<NCTA_, 256, SM_TOTAL>>>(xwb, Wh1, Wi2, Wh2, b2);
    head_kernel<<<B_, 256>>>(Wd1, bd1, Wd2, bd2, out);
}

// round 13
// speedup vs baseline: 4.6141x; 1.0352x over previous
#include <cuda_runtime.h>
#include <cuda_bf16.h>
#include <math.h>

#define B_    64
#define T_    512
#define F_    64
#define H_    512
#define G_    2048          // 4*H
#define M_    (B_*T_)       // 32768
#define NCTA_ 128
#define HB_   (H_*B_)       // 32768

typedef unsigned long long ull;

// ---------------- packed f32x2 helpers (for gemm_atb) ----------------
__device__ __forceinline__ void ffma2(ull& acc, ull a, ull b) {
    asm("fma.rn.f32x2 %0, %1, %2, %0;" : "+l"(acc) : "l"(a), "l"(b));
}
__device__ __forceinline__ ull pack2(float lo, float hi) {
    ull r; asm("mov.b64 %0, {%1, %2};" : "=l"(r) : "f"(lo), "f"(hi)); return r;
}
__device__ __forceinline__ void unpack2(ull v, float& lo, float& hi) {
    asm("mov.b64 {%0, %1}, %2;" : "=f"(lo), "=f"(hi) : "l"(v));
}

// ---------------- cp.async helpers ----------------
__device__ __forceinline__ void cp_async16(void* smem_dst, const void* gsrc) {
    unsigned s = (unsigned)__cvta_generic_to_shared(smem_dst);
    asm volatile("cp.async.cg.shared.global [%0], [%1], 16;" :: "r"(s), "l"(gsrc));
}
__device__ __forceinline__ void cp_commit() {
    asm volatile("cp.async.commit_group;");
}
template <int N>
__device__ __forceinline__ void cp_wait() {
    asm volatile("cp.async.wait_group %0;" :: "n"(N));
}

// ---------------- HMMA helpers (baseline PTX, proven rounds 9/12) ----------------
#define SWZ128(x) ((x) ^ (((x) >> 3) & 0x70))
#define SWZW(x)   ((x) ^ (((x) >> 6) & 0x70))      // for 1024B-row weight tiles

__device__ __forceinline__ void ldsm_x4(unsigned& r0, unsigned& r1, unsigned& r2, unsigned& r3,
                                        unsigned addr) {
    asm volatile("ldmatrix.sync.aligned.m8n8.x4.shared.b16 {%0,%1,%2,%3}, [%4];"
                 : "=r"(r0), "=r"(r1), "=r"(r2), "=r"(r3) : "r"(addr));
}
__device__ __forceinline__ void ldsm_x2(unsigned& r0, unsigned& r1, unsigned addr) {
    asm volatile("ldmatrix.sync.aligned.m8n8.x2.shared.b16 {%0,%1}, [%2];"
                 : "=r"(r0), "=r"(r1) : "r"(addr));
}
__device__ __forceinline__ void mma_bf16(float* c, const unsigned* a, const unsigned* b) {
    asm volatile("mma.sync.aligned.m16n8k16.row.col.f32.bf16.bf16.f32 "
                 "{%0,%1,%2,%3}, {%4,%5,%6,%7}, {%8,%9}, {%0,%1,%2,%3};"
                 : "+f"(c[0]), "+f"(c[1]), "+f"(c[2]), "+f"(c[3])
                 : "r"(a[0]), "r"(a[1]), "r"(a[2]), "r"(a[3]), "r"(b[0]), "r"(b[1]));
}

// ---------------- scratch (static device allocations only) ----------------
__device__ float g_xT[(size_t)F_ * M_];       //   8 MB : x transposed [F][M]
__device__ float g_xw[(size_t)M_ * G_];       // 256 MB : xW1 (+b1) [M][G]
__device__ float g_h2bufT[2 * HB_];           // fp32 h2 (for head), [buf][k][b]
__device__ __nv_bfloat16 g_h1hi[2 * HB_];     // split-bf16 h buffers, [buf][b][k]
__device__ __nv_bfloat16 g_h1lo[2 * HB_];
__device__ __nv_bfloat16 g_h2hi[2 * HB_];
__device__ __nv_bfloat16 g_h2lo[2 * HB_];
__device__ unsigned g_cnt8[8 * 32];
__device__ unsigned g_gen8[8 * 32];
__device__ unsigned g_done8;

// ---------------- smem layout (bytes) for lstm_fused ----------------
#define SM_W1HI   0
#define SM_W1LO   16384
#define SM_WI2HI  32768
#define SM_WI2LO  49152
#define SM_WH2HI  65536
#define SM_WH2LO  81920
#define SM_RING   98304      // 3 slots x 32768 (hi 16384 | lo 16384; 2 half-tiles each)
#define SM_RED    196608     // 24 tiles x 256 floats = 24576 B
#define SM_C1     221184     // 256 floats
#define SM_C2     222208
#define SM_B2     223232     // 16 floats
#define SM_TOTAL  223296

// acquire load
__device__ __forceinline__ unsigned ld_acq(const unsigned* p) {
    unsigned v;
    asm volatile("ld.acquire.gpu.global.u32 %0, [%1];" : "=r"(v) : "l"(p));
    return v;
}

// ---------------- grid-wide barrier (proven rounds 6-12) ----------------
__device__ __forceinline__ void grid_barrier()
{
    __syncthreads();
    if (threadIdx.x == 0) {
        const unsigned lane = blockIdx.x & 7u;
        unsigned* cntp = &g_cnt8[lane * 32];
        unsigned* genp = &g_gen8[lane * 32];
        __threadfence();
        unsigned gen = ld_acq(genp);
        unsigned arrived = atomicAdd(cntp, 1u);
        if (arrived == 15u) {
            atomicExch(cntp, 0u);
            unsigned d = atomicAdd(&g_done8, 1u);
            if (d == 7u) {
                atomicExch(&g_done8, 0u);
                __threadfence();
#pragma unroll
                for (int l = 0; l < 8; l++)
                    atomicAdd(&g_gen8[l * 32], 1u);
            } else {
                while (ld_acq(genp) == gen) { __nanosleep(32); }
            }
        } else {
            while (ld_acq(genp) == gen) { __nanosleep(32); }
        }
        __threadfence();
    }
    __syncthreads();
}

// ---------------- x transpose ----------------
__global__ void __launch_bounds__(256) transpose_x(const float* __restrict__ x,
                                                   float* __restrict__ xT)
{
    __shared__ float tile[32][33];
    const int m0 = blockIdx.x * 32;
    const int f0 = blockIdx.y * 32;
    const int tx = threadIdx.x, ty = threadIdx.y;
#pragma unroll
    for (int i = 0; i < 32; i += 8)
        tile[ty + i][tx] = x[(size_t)(m0 + ty + i) * F_ + f0 + tx];
    __syncthreads();
#pragma unroll
    for (int i = 0; i < 32; i += 8)
        xT[(size_t)(f0 + ty + i) * M_ + m0 + tx] = tile[tx][ty + i];
}

// ---------------- GEMM (FFMA2, proven) — GEMM1: xW1 ----------------
__global__ void __launch_bounds__(256) gemm_atb(const float* __restrict__ AT,
                                                const float* __restrict__ Bm,
                                                const float* __restrict__ bias,
                                                float* __restrict__ C,
                                                int M, int N, int K)
{
    __shared__ float As[2][16 * 64];
    __shared__ float Bs[2][16 * 64];
    const int tid = threadIdx.x;
    const int tx = tid & 15, ty = tid >> 4;
    const int m0 = blockIdx.y * 64, n0 = blockIdx.x * 64;
    const int lr = tid >> 4, lc4 = (tid & 15) * 4;

    const float* ap = AT + (size_t)lr * M + m0 + lc4;
    const float* bp = Bm + (size_t)lr * N + n0 + lc4;
    float4 aReg = *(const float4*)ap;
    float4 bReg = *(const float4*)bp;

    ull accP[4][2];
#pragma unroll
    for (int i = 0; i < 4; i++) { accP[i][0] = 0ull; accP[i][1] = 0ull; }

    const int NT = K >> 4;
    for (int kt = 0; kt < NT; kt++) {
        const int cur = kt & 1;
        *(float4*)&As[cur][lr * 64 + lc4] = aReg;
        *(float4*)&Bs[cur][lr * 64 + lc4] = bReg;
        __syncthreads();
        if (kt + 1 < NT) {
            aReg = *(const float4*)(ap + (size_t)(kt + 1) * 16 * M);
            bReg = *(const float4*)(bp + (size_t)(kt + 1) * 16 * N);
        }
#pragma unroll
        for (int kk = 0; kk < 16; kk++) {
            float4 a = *(const float4*)&As[cur][kk * 64 + ty * 4];
            ulonglong2 bv = *(const ulonglong2*)&Bs[cur][kk * 64 + tx * 4];
            ull a0 = pack2(a.x, a.x);
            ull a1 = pack2(a.y, a.y);
            ull a2 = pack2(a.z, a.z);
            ull a3 = pack2(a.w, a.w);
            ffma2(accP[0][0], a0, bv.x); ffma2(accP[0][1], a0, bv.y);
            ffma2(accP[1][0], a1, bv.x); ffma2(accP[1][1], a1, bv.y);
            ffma2(accP[2][0], a2, bv.x); ffma2(accP[2][1], a2, bv.y);
            ffma2(accP[3][0], a3, bv.x); ffma2(accP[3][1], a3, bv.y);
        }
    }
    float acc[4][4];
#pragma unroll
    for (int i = 0; i < 4; i++) {
        unpack2(accP[i][0], acc[i][0], acc[i][1]);
        unpack2(accP[i][1], acc[i][2], acc[i][3]);
    }
    float4 bv = *(const float4*)(bias + n0 + tx * 4);
#pragma unroll
    for (int i = 0; i < 4; i++) {
        float4 o;
        o.x = acc[i][0] + bv.x;
        o.y = acc[i][1] + bv.y;
        o.z = acc[i][2] + bv.z;
        o.w = acc[i][3] + bv.w;
        *(float4*)&C[(size_t)(m0 + ty * 4 + i) * N + n0 + tx * 4] = o;
    }
}

// ---------------- per-phase MMA body (round-12 geometry; ks range + half offset) --------
template <int NKS>
__device__ __forceinline__ void mma_run(float acc[2][4], unsigned sbase, unsigned slot,
                                        unsigned wbase, int mt, int kk0, int ks0,
                                        int aRow, int aKof, int bRow, int bKof)
{
#pragma unroll
    for (int j = 0; j < NKS; j++) {
        int ks = ks0 + j;
        unsigned aoff = (unsigned)((ks >> 2) * 8192)
                      + SWZ128((unsigned)((mt * 16 + aRow) * 128 + ((ks & 3) * 16 + aKof) * 2));
        unsigned ah[4], al[4];
        ldsm_x4(ah[0], ah[1], ah[2], ah[3], slot + aoff);
        ldsm_x4(al[0], al[1], al[2], al[3], slot + 16384 + aoff);
        int kg = kk0 + ks * 16;
#pragma unroll
        for (int nt = 0; nt < 2; nt++) {
            unsigned bh[2], bl[2];
            unsigned boff = SWZW((unsigned)((nt * 8 + bRow) * 1024 + (kg + bKof) * 2));
            ldsm_x2(bh[0], bh[1], sbase + wbase + boff);
            ldsm_x2(bl[0], bl[1], sbase + wbase + 16384 + boff);
            mma_bf16(acc[nt], ah, bh);
            mma_bf16(acc[nt], ah, bl);
            mma_bf16(acc[nt], al, bh);
        }
    }
}

// ---------------- fused two-layer persistent LSTM — tensor-core matmuls ----------------
// 128 CTAs, 256 threads. CTA owns hidden cols hc0..hc0+3 of both layers.
// Step s: z1(t=s) = xw + h1[s-1]@Wh1 ; z2(t=s-1) = h1[s-1]@Wi2 + h2[s-2]@Wh2 + b2.
// 8 staging phases of 32KB (4 h1, 4 h2), ring of 3, all 8 warps busy every phase.
__global__ void __launch_bounds__(256, 1) lstm_fused(const float* __restrict__ xw,
                                                     const float* __restrict__ Wh1,
                                                     const float* __restrict__ Wi2,
                                                     const float* __restrict__ Wh2,
                                                     const float* __restrict__ b2)
{
    extern __shared__ char smc[];
    float* red  = (float*)(smc + SM_RED);
    float* c1_s = (float*)(smc + SM_C1);
    float* c2_s = (float*)(smc + SM_C2);
    float* b2_s = (float*)(smc + SM_B2);
    const unsigned sbase = (unsigned)__cvta_generic_to_shared(smc);

    const int tid  = threadIdx.x;
    const int wid  = tid >> 5, lane = tid & 31;
    const int grp  = lane >> 2, tig = lane & 3;
    const int aRow = lane & 15;
    const int aKof = (lane >> 4) << 3;
    const int bRow = lane & 7;
    const int bKof = ((lane >> 3) & 1) << 3;
    const int hc0  = blockIdx.x * 4;

    // ---- one-time init: weights -> smem bf16 hi/lo, [col][k] with SWZW ----
    for (int i = tid; i < 16 * 512; i += 256) {
        int k = i >> 4, col = i & 15;
        size_t go = (size_t)k * G_ + (col >> 2) * H_ + hc0 + (col & 3);
        unsigned off = SWZW((unsigned)(col * 1024 + k * 2));
        float v; __nv_bfloat16 h;
        v = Wh1[go]; h = __float2bfloat16(v);
        *(__nv_bfloat16*)(smc + SM_W1HI + off) = h;
        *(__nv_bfloat16*)(smc + SM_W1LO + off) = __float2bfloat16(v - __bfloat162float(h));
        v = Wi2[go]; h = __float2bfloat16(v);
        *(__nv_bfloat16*)(smc + SM_WI2HI + off) = h;
        *(__nv_bfloat16*)(smc + SM_WI2LO + off) = __float2bfloat16(v - __bfloat162float(h));
        v = Wh2[go]; h = __float2bfloat16(v);
        *(__nv_bfloat16*)(smc + SM_WH2HI + off) = h;
        *(__nv_bfloat16*)(smc + SM_WH2LO + off) = __float2bfloat16(v - __bfloat162float(h));
    }
    if (tid < 16) b2_s[tid] = b2[(tid >> 2) * H_ + hc0 + (tid & 3)];
    c1_s[tid] = 0.f;
    c2_s[tid] = 0.f;
    // zero this CTA's h slices (both parities, all buffers)
    for (int i = tid; i < 512; i += 256) {
        int bufi = i >> 8, rem = i & 255;
        int c = rem >> 6, b = rem & 63;
        int idx = bufi * HB_ + b * 512 + hc0 + c;
        __nv_bfloat16 z = __float2bfloat16(0.f);
        g_h1hi[idx] = z; g_h1lo[idx] = z;
        g_h2hi[idx] = z; g_h2lo[idx] = z;
        g_h2bufT[bufi * HB_ + (hc0 + c) * B_ + b] = 0.f;
    }
    __threadfence();
    grid_barrier();

    const int bb = tid >> 2, cc_hid = tid & 3;     // reducer mapping: (batch, hidden)

    for (int s = 0; s <= T_; s++) {
        const int r1 = (s + 1) & 1;     // h1[s-1] parity
        const int r2 = s & 1;           // h2[s-2] parity
        const int w1 = s & 1;           // h1[s] write parity
        const int w2 = (s + 1) & 1;     // h2[s-1] write parity

        const __nv_bfloat16* h1hiR = g_h1hi + r1 * HB_;
        const __nv_bfloat16* h1loR = g_h1lo + r1 * HB_;
        const __nv_bfloat16* h2hiR = g_h2hi + r2 * HB_;
        const __nv_bfloat16* h2loR = g_h2lo + r2 * HB_;

        // xw prefetch (per reducer thread), guarded
        float xv[4] = {0.f, 0.f, 0.f, 0.f};
        if (s < T_) {
            size_t xb = (size_t)(bb * T_ + s) * G_ + hc0 + cc_hid;
#pragma unroll
            for (int g = 0; g < 4; g++) xv[g] = __ldg(xw + xb + g * H_);
        }

        // phase staging: ci 0-3 = h1 (k0 = ci*128), 4-7 = h2; slot = ci%3 (32KB)
        auto issue_chunk = [&](int ci) {
            const __nv_bfloat16 *hi, *lo; int k0;
            if (ci < 4) { hi = h1hiR; lo = h1loR; k0 = ci * 128; }
            else        { hi = h2hiR; lo = h2loR; k0 = (ci - 4) * 128; }
            char* dst = smc + SM_RING + (ci % 3) * 32768;
#pragma unroll
            for (int rep = 0; rep < 4; rep++) {
                int i = tid + rep * 256;           // 0..1023
                int row = i >> 4, seg = i & 15;
                unsigned o = (unsigned)((seg >> 3) * 8192)
                           + SWZ128((unsigned)(row * 128 + (seg & 7) * 16));
                cp_async16(dst + o,         hi + row * 512 + k0 + seg * 8);
                cp_async16(dst + 16384 + o, lo + row * 512 + k0 + seg * 8);
            }
            cp_commit();
        };

        float accA[2][4], accB[2][4], accC[2][4];
#pragma unroll
        for (int i = 0; i < 2; i++)
#pragma unroll
            for (int e = 0; e < 4; e++) { accA[i][e] = 0.f; accB[i][e] = 0.f; accC[i][e] = 0.f; }

        issue_chunk(0);
        issue_chunk(1);

#pragma unroll
        for (int ck = 0; ck < 8; ck++) {
            if (ck < 7) { cp_wait<1>(); } else { cp_wait<0>(); }
            __syncthreads();
            if (ck < 6) issue_chunk(ck + 2);

            const unsigned slot = sbase + SM_RING + (unsigned)(ck % 3) * 32768;
            const int k0 = (ck & 3) * 128;
            if (ck < 4) {
                if ((ck >> 1) == (wid >> 2))
                    mma_run<8>(accA, sbase, slot, SM_W1HI,  wid & 3, k0, 0,
                               aRow, aKof, bRow, bKof);
                else
                    mma_run<8>(accB, sbase, slot, SM_WI2HI, wid & 3, k0, 0,
                               aRow, aKof, bRow, bKof);
            } else {
                mma_run<4>(accC, sbase, slot, SM_WH2HI, wid >> 1, k0, (wid & 1) * 4,
                           aRow, aKof, bRow, bKof);
            }
        }

        // ---- write fp32 partial tiles to red (same layout/mapping as round 12) ----
        auto store_tile = [&](int tileId, float acc[2][4]) {
            float* base = red + tileId * 256;
#pragma unroll
            for (int nt = 0; nt < 2; nt++) {
                int col = nt * 8 + tig * 2;
                base[grp * 16 + col]           = acc[nt][0];
                base[grp * 16 + col + 1]       = acc[nt][1];
                base[(grp + 8) * 16 + col]     = acc[nt][2];
                base[(grp + 8) * 16 + col + 1] = acc[nt][3];
            }
        };
        store_tile((wid & 3) * 2 + (wid >> 2), accA);                 // z1 tiles 0-7
        store_tile(8 + (wid & 3) * 2 + (1 - (wid >> 2)), accB);       // Wi2 tiles 8-15
        store_tile(16 + (wid >> 1) * 2 + (wid & 1), accC);            // Wh2 tiles 16-23
        __syncthreads();

        // ---- reduction + gates + state update: thread = (bb, cc_hid) ----
        {
            const int mt = bb >> 4, ri = bb & 15;
            const int rbase = ri * 16;
            if (s < T_) {
                float z[4];
#pragma unroll
                for (int g = 0; g < 4; g++) {
                    int col = g * 4 + cc_hid;
                    z[g] = xv[g] + red[(mt * 2) * 256 + rbase + col]
                                 + red[(mt * 2 + 1) * 256 + rbase + col];
                }
                float ig = 1.f / (1.f + expf(-z[0]));
                float fg = 1.f / (1.f + expf(-z[1]));
                float gg = tanhf(z[2]);
                float og = 1.f / (1.f + expf(-z[3]));
                float c1 = fmaf(fg, c1_s[tid], ig * gg);
                c1_s[tid] = c1;
                float h1 = og * tanhf(c1);
                __nv_bfloat16 hi = __float2bfloat16(h1);
                int idx = w1 * HB_ + bb * 512 + hc0 + cc_hid;
                g_h1hi[idx] = hi;
                g_h1lo[idx] = __float2bfloat16(h1 - __bfloat162float(hi));
            }
            if (s >= 1) {
                float z[4];
#pragma unroll
                for (int g = 0; g < 4; g++) {
                    int col = g * 4 + cc_hid;
                    z[g] = b2_s[col]
                         + red[(8 + mt * 2) * 256 + rbase + col]
                         + red[(8 + mt * 2 + 1) * 256 + rbase + col]
                         + red[(16 + mt * 2) * 256 + rbase + col]
                         + red[(16 + mt * 2 + 1) * 256 + rbase + col];
                }
                float ig = 1.f / (1.f + expf(-z[0]));
                float fg = 1.f / (1.f + expf(-z[1]));
                float gg = tanhf(z[2]);
                float og = 1.f / (1.f + expf(-z[3]));
                float c2 = fmaf(fg, c2_s[tid], ig * gg);
                c2_s[tid] = c2;
                float h2 = og * tanhf(c2);
                __nv_bfloat16 hi = __float2bfloat16(h2);
                int idx = w2 * HB_ + bb * 512 + hc0 + cc_hid;
                g_h2hi[idx] = hi;
                g_h2lo[idx] = __float2bfloat16(h2 - __bfloat162float(hi));
                g_h2bufT[w2 * HB_ + (hc0 + cc_hid) * B_ + bb] = h2;   // fp32 for head
            }
        }
        grid_barrier();
    }
}

// ---------------- head: out[b] = relu(relu(h@Wd1 + bd1) @ Wd2 + bd2) ----------------
__global__ void __launch_bounds__(256) head_kernel(const float* __restrict__ Wd1,
                                                   const float* __restrict__ bd1,
                                                   const float* __restrict__ Wd2,
                                                   const float* __restrict__ bd2,
                                                   float* __restrict__ out)
{
    const int b = blockIdx.x;
    const int j = threadIdx.x;
    const float* hT = g_h2bufT + HB_;          // h2[511] written at s=512 into parity 1
    float acc = 0.f;
#pragma unroll 8
    for (int k = 0; k < H_; k++)
        acc = fmaf(hT[k * B_ + b], Wd1[k * (H_ / 2) + j], acc);
    float t1 = fmaxf(acc + bd1[j], 0.f);
    float p  = t1 * Wd2[j];
    __shared__ float s[256];
    s[j] = p;
    __syncthreads();
    for (int off = 128; off; off >>= 1) {
        if (j < off) s[j] += s[j + off];
        __syncthreads();
    }
    if (j == 0) out[b] = fmaxf(s[0] + bd2[0], 0.f);
}

// ---------------- launch ----------------
extern "C" void kernel_launch(void* const* d_in, const int* in_sizes, int n_in,
                              void* d_out, int out_size)
{
    (void)in_sizes; (void)n_in; (void)out_size;
    const float* x   = (const float*)d_in[0];
    const float* Wi1 = (const float*)d_in[2];
    const float* Wh1 = (const float*)d_in[3];
    const float* b1  = (const float*)d_in[4];
    const float* Wi2 = (const float*)d_in[5];
    const float* Wh2 = (const float*)d_in[6];
    const float* b2  = (const float*)d_in[7];
    const float* Wd1 = (const float*)d_in[8];
    const float* bd1 = (const float*)d_in[9];
    const float* Wd2 = (const float*)d_in[10];
    const float* bd2 = (const float*)d_in[11];
    float* out = (float*)d_out;

    float *xT, *xwb;
    cudaGetSymbolAddress((void**)&xT,  g_xT);
    cudaGetSymbolAddress((void**)&xwb, g_xw);

    cudaFuncSetAttribute(lstm_fused,
                         cudaFuncAttributeMaxDynamicSharedMemorySize, SM_TOTAL);

    transpose_x<<<dim3(1024, 2), dim3(32, 8)>>>(x, xT);
    gemm_atb<<<dim3(G_ / 64, M_ / 64), 256>>>(xT, Wi1, b1, xwb, M_, G_, F_);
    lstm_fused<<<NCTA_, 256, SM_TOTAL>>>(xwb, Wh1, Wi2, Wh2, b2);
    head_kernel<<<B_, 256>>>(Wd1, bd1, Wd2, bd2, out);
}